// round 4
// baseline (speedup 1.0000x reference)
#include <cuda_runtime.h>
#include <cuda_bf16.h>

typedef unsigned int u32;
typedef unsigned short us16;

#define NB 8
#define NC 512
#define NQ 64
#define NHW 4096
#define BCHW (NB*NC*NHW)
#define BQHW (NB*NQ*NHW)
#define CHW  (NC*NHW)
#define QHW  (NQ*NHW)

// ------------------------- device scratch -------------------------
__device__ __align__(16) us16  g_x2b [BCHW];
__device__ __align__(16) us16  g_x1b [BCHW];
__device__ __align__(16) us16  g_xT2 [BCHW];
__device__ __align__(16) us16  g_xT1 [BCHW];
__device__ __align__(16) float g_q   [BQHW];
__device__ __align__(16) float g_k   [BQHW];
__device__ __align__(16) float g_qT  [BQHW];
__device__ __align__(16) float g_kT  [BQHW];
__device__ __align__(16) float g_att [NB*NHW*128];
__device__ __align__(16) us16  g_attb[NB*NHW*128];
__device__ __align__(16) us16  g_aggR2[BCHW];
__device__ __align__(16) us16  g_aggC2[BCHW];
__device__ __align__(16) us16  g_aggR1[BCHW];
__device__ __align__(16) us16  g_aggC1[BCHW];
__device__ __align__(16) us16  g_agg2[BCHW];
__device__ __align__(16) us16  g_agg1[BCHW];
__device__ __align__(16) us16  g_wqk[128*NC];
__device__ __align__(16) us16  g_wv [NC*NC];

// ------------------------- helpers -------------------------
__device__ __forceinline__ us16 f2b(float f){
    __nv_bfloat16 h = __float2bfloat16(f);
    return *reinterpret_cast<us16*>(&h);
}
__device__ __forceinline__ float b2f(us16 u){
    __nv_bfloat16 h; *reinterpret_cast<us16*>(&h) = u;
    return __bfloat162float(h);
}
__device__ __forceinline__ u32 pk2(float a, float b){
    return (u32)f2b(a) | ((u32)f2b(b) << 16);
}
__device__ __forceinline__ void mma_bf16(float* d, const u32* a, const u32* b){
    asm volatile(
        "mma.sync.aligned.m16n8k16.row.col.f32.bf16.bf16.f32 "
        "{%0,%1,%2,%3}, {%4,%5,%6,%7}, {%8,%9}, {%0,%1,%2,%3};\n"
        : "+f"(d[0]), "+f"(d[1]), "+f"(d[2]), "+f"(d[3])
        : "r"(a[0]), "r"(a[1]), "r"(a[2]), "r"(a[3]), "r"(b[0]), "r"(b[1]));
}

// -------- convert x -> bf16 (normal + transposed hw plane) --------
__global__ __launch_bounds__(256) void k_conv_tr(const float* __restrict__ x2,
                                                 const float* __restrict__ x1){
    int plane = blockIdx.x, which = blockIdx.y, t = threadIdx.x;
    const float* x  = (which ? x1    : x2   ) + (size_t)plane * 4096;
    us16*       on  = (which ? g_x1b : g_x2b) + (size_t)plane * 4096;
    us16*       ot  = (which ? g_xT1 : g_xT2) + (size_t)plane * 4096;
    __shared__ float sm[64][65];
#pragma unroll
    for (int j = 0; j < 16; j++){
        int idx = j*256 + t;
        float v = x[idx];
        sm[idx>>6][idx&63] = v;
        on[idx] = f2b(v);
    }
    __syncthreads();
#pragma unroll
    for (int j = 0; j < 16; j++){
        int idx = j*256 + t;
        ot[idx] = f2b(sm[idx&63][idx>>6]);
    }
}

// -------- convert weights --------
__global__ __launch_bounds__(256) void k_conv_w(const float* __restrict__ qw,
                                                const float* __restrict__ kw,
                                                const float* __restrict__ vw){
    int i = blockIdx.x * 256 + threadIdx.x;
    if (i < 128 * NC){
        int o = i >> 9, c = i & 511;
        g_wqk[i] = f2b(o < 64 ? qw[o*NC + c] : kw[(o-64)*NC + c]);
    } else if (i < 128*NC + NC*NC){
        int j = i - 128*NC;
        g_wv[j] = f2b(vw[j]);
    }
}

// -------- main bf16 GEMM (128x128 tile, K=512) --------
// mode 0: [q_w;k_w](128x512) * x2b -> q,k (fp32 + bias)
// mode 1: v_w(512x512) * agg -> out = gamma*(acc + v_b) + xres
__global__ __launch_bounds__(256) void k_gemm(int mode, int sel,
    const float* __restrict__ bias0, const float* __restrict__ bias1,
    const float* __restrict__ xres, const float* __restrict__ gam,
    float* __restrict__ out)
{
    __shared__ __align__(16) us16 As[128][40];   // [m][k]
    __shared__ __align__(16) us16 Bs[32][136];   // [k][n]
    int b = blockIdx.z, t = threadIdx.x;
    int n0 = blockIdx.x * 128, m0 = blockIdx.y * 128;
    const us16* A  = mode ? g_wv : g_wqk;
    const us16* Bp = (mode ? (sel ? g_agg1 : g_agg2) : g_x2b) + (size_t)b * CHW;
    int warp = t >> 5, lane = t & 31;
    int wm = warp >> 2, wn = warp & 3;           // 2x4 warps -> 64x32 each
    int r = lane >> 2, cp = (lane & 3) * 2;

    float acc[4][4][4];
#pragma unroll
    for (int i = 0; i < 4; i++)
#pragma unroll
        for (int j = 0; j < 4; j++)
#pragma unroll
            for (int q2 = 0; q2 < 4; q2++) acc[i][j][q2] = 0.f;

    for (int k0 = 0; k0 < NC; k0 += 32){
        __syncthreads();
#pragma unroll
        for (int cc = 0; cc < 2; cc++){
            int ch = t + cc*256;
            int row = ch >> 2, cl = (ch & 3) * 8;
            *(uint4*)&As[row][cl] = *(const uint4*)(A + (size_t)(m0+row)*NC + k0 + cl);
            int kr = ch >> 4, nb = (ch & 15) * 8;
            *(uint4*)&Bs[kr][nb] = *(const uint4*)(Bp + (size_t)(k0+kr)*NHW + n0 + nb);
        }
        __syncthreads();
#pragma unroll
        for (int ks = 0; ks < 32; ks += 16){
            u32 af[4][4], bfr[4][2];
#pragma unroll
            for (int mi = 0; mi < 4; mi++){
                int rr = wm*64 + mi*16 + r;
                af[mi][0] = *(const u32*)&As[rr  ][ks+cp  ];
                af[mi][1] = *(const u32*)&As[rr+8][ks+cp  ];
                af[mi][2] = *(const u32*)&As[rr  ][ks+cp+8];
                af[mi][3] = *(const u32*)&As[rr+8][ks+cp+8];
            }
#pragma unroll
            for (int ni = 0; ni < 4; ni++){
                u32 sa = (u32)__cvta_generic_to_shared(&Bs[ks + (lane & 15)][wn*32 + ni*8]);
                asm volatile("ldmatrix.sync.aligned.m8n8.x2.trans.shared.b16 {%0,%1}, [%2];"
                             : "=r"(bfr[ni][0]), "=r"(bfr[ni][1]) : "r"(sa));
            }
#pragma unroll
            for (int mi = 0; mi < 4; mi++)
#pragma unroll
                for (int ni = 0; ni < 4; ni++)
                    mma_bf16(acc[mi][ni], af[mi], bfr[ni]);
        }
    }

    float gval = mode ? gam[0] : 0.f;
#pragma unroll
    for (int mi = 0; mi < 4; mi++){
#pragma unroll
        for (int ni = 0; ni < 4; ni++){
            int ng = n0 + wn*32 + ni*8 + cp;
#pragma unroll
            for (int rr2 = 0; rr2 < 2; rr2++){
                int oo = m0 + wm*64 + mi*16 + r + rr2*8;
                float a0 = acc[mi][ni][rr2*2 + 0];
                float a1 = acc[mi][ni][rr2*2 + 1];
                if (mode == 0){
                    if (oo < 64){
                        float bb = bias0[oo];
                        *(float2*)&g_q[(size_t)(b*NQ + oo)*NHW + ng] = make_float2(a0+bb, a1+bb);
                    } else {
                        float bb = bias1[oo-64];
                        *(float2*)&g_k[(size_t)(b*NQ + oo-64)*NHW + ng] = make_float2(a0+bb, a1+bb);
                    }
                } else {
                    float bb = bias0[oo];
                    size_t oi = (size_t)(b*NC + oo)*NHW + ng;
                    float2 xr = *(const float2*)(xres + oi);
                    *(float2*)(out + oi) = make_float2(gval*(a0+bb)+xr.x, gval*(a1+bb)+xr.y);
                }
            }
        }
    }
}

// -------- q,k fp32 plane transpose: [h][w] -> [w][h] --------
__global__ __launch_bounds__(256) void k_tr_qk(){
    int p = blockIdx.x, which = blockIdx.y, t = threadIdx.x;
    const float* src = (which ? g_k  : g_q ) + (size_t)p*4096;
    float*       dst = (which ? g_kT : g_qT) + (size_t)p*4096;
    __shared__ float sm[64][65];
#pragma unroll
    for (int j = 0; j < 16; j++){
        int idx = j*256 + t;
        sm[idx>>6][idx&63] = src[idx];
    }
    __syncthreads();
#pragma unroll
    for (int j = 0; j < 16; j++){
        int idx = j*256 + t;
        dst[idx] = sm[idx&63][idx>>6];
    }
}

// -------- energies (fp32): dir0 = H (uses qT/kT, fixed w), dir1 = W (fixed h) --------
__global__ __launch_bounds__(256) void k_energy(){
    __shared__ float Qs[64][68], Ks[64][68];
    int plane = blockIdx.x, b = blockIdx.y, dir = blockIdx.z, t = threadIdx.x;
    const float* qb = (dir ? g_q : g_qT) + (size_t)b*QHW + plane*64;
    const float* kb = (dir ? g_k : g_kT) + (size_t)b*QHW + plane*64;
#pragma unroll
    for (int j = 0; j < 16; j++){
        int idx = j*256 + t;
        int cq = idx >> 6, i = idx & 63;
        Qs[cq][i] = qb[(size_t)cq*4096 + i];
        Ks[cq][i] = kb[(size_t)cq*4096 + i];
    }
    __syncthreads();
    int i = t >> 2, j0 = (t & 3) * 16;
    float acc[16];
#pragma unroll
    for (int u = 0; u < 16; u++) acc[u] = 0.f;
    for (int cq = 0; cq < 64; cq++){
        float qv = Qs[cq][i];
#pragma unroll
        for (int u4 = 0; u4 < 4; u4++){
            float4 kv = *(const float4*)&Ks[cq][j0 + u4*4];
            acc[u4*4+0] += qv * kv.x;
            acc[u4*4+1] += qv * kv.y;
            acc[u4*4+2] += qv * kv.z;
            acc[u4*4+3] += qv * kv.w;
        }
    }
    size_t pix; int joff;
    if (dir == 0){ pix = (size_t)b*4096 + (size_t)i*64 + plane;   joff = 0;  }
    else         { pix = (size_t)b*4096 + (size_t)plane*64 + i;   joff = 64; }
    float* dst = g_att + pix*128 + joff + j0;
#pragma unroll
    for (int u4 = 0; u4 < 4; u4++)
        *(float4*)(dst + u4*4) = make_float4(acc[u4*4], acc[u4*4+1], acc[u4*4+2], acc[u4*4+3]);
}

// -------- softmax over 128, write bf16 --------
__global__ __launch_bounds__(256) void k_softmax(){
    int t = threadIdx.x;
    size_t pix = (size_t)blockIdx.x*8 + (t>>5);
    int lane = t & 31;
    float4 v = *(const float4*)(g_att + pix*128 + lane*4);
    float m = fmaxf(fmaxf(v.x, v.y), fmaxf(v.z, v.w));
#pragma unroll
    for (int o = 16; o; o >>= 1) m = fmaxf(m, __shfl_xor_sync(0xffffffffu, m, o));
    float e0 = __expf(v.x - m), e1 = __expf(v.y - m);
    float e2 = __expf(v.z - m), e3 = __expf(v.w - m);
    float s = e0 + e1 + e2 + e3;
#pragma unroll
    for (int o = 16; o; o >>= 1) s += __shfl_xor_sync(0xffffffffu, s, o);
    float inv = 1.f / s;
    u32 lo = pk2(e0*inv, e1*inv), hi = pk2(e2*inv, e3*inv);
    *(uint2*)(g_attb + pix*128 + lane*4) = make_uint2(lo, hi);
}

// -------- aggregation: agg[c][n] = sum_j X[c][j] * att[n][j] (bf16 mma) --------
// dir0: fixed w=plane, X=xT, j=H, out -> aggC[b][c][w][h]
// dir1: fixed h=plane, X=xb, j=W, out -> aggR[b][c][h][w]
__global__ __launch_bounds__(256) void k_agg(){
    __shared__ __align__(16) us16 Bs[64][72];    // [n][k]
    __shared__ __align__(16) us16 As[128][72];   // [c][k]
    int plane = blockIdx.x, b = blockIdx.y, dir = blockIdx.z, t = threadIdx.x;
    const us16* X2 = (dir ? g_x2b  : g_xT2 ) + (size_t)b*CHW + plane*64;
    const us16* X1 = (dir ? g_x1b  : g_xT1 ) + (size_t)b*CHW + plane*64;
    us16*       O2 = (dir ? g_aggR2: g_aggC2) + (size_t)b*CHW + plane*64;
    us16*       O1 = (dir ? g_aggR1: g_aggC1) + (size_t)b*CHW + plane*64;
    const us16* attp; int istride;
    if (dir == 0){ attp = g_attb + ((size_t)b*4096 + plane)*128;            istride = 8192; }
    else         { attp = g_attb + ((size_t)b*4096 + (size_t)plane*64)*128 + 64; istride = 128; }

    int warp = t >> 5, lane = t & 31;
    int r = lane >> 2, cp = (lane & 3) * 2;

#pragma unroll
    for (int it = 0; it < 2; it++){
        int job = it*256 + t;
        int i = job >> 3, seg = job & 7;
        *(uint4*)&Bs[i][seg*8] = *(const uint4*)(attp + (size_t)i*istride + seg*8);
    }

    for (int c0 = 0; c0 < NC; c0 += 128){
        for (int tsel = 0; tsel < 2; tsel++){
            const us16* Xp = (tsel ? X1 : X2) + (size_t)c0 * 4096;
            us16*       Op = (tsel ? O1 : O2) + (size_t)c0 * 4096;
            __syncthreads();
#pragma unroll
            for (int it = 0; it < 4; it++){
                int job = it*256 + t;
                int rr = job >> 3, seg = job & 7;
                *(uint4*)&As[rr][seg*8] = *(const uint4*)(Xp + (size_t)rr*4096 + seg*8);
            }
            __syncthreads();
            float acc[8][4];
#pragma unroll
            for (int nt = 0; nt < 8; nt++)
#pragma unroll
                for (int q2 = 0; q2 < 4; q2++) acc[nt][q2] = 0.f;
#pragma unroll
            for (int ks = 0; ks < 64; ks += 16){
                u32 af[4];
                int rr = warp*16 + r;
                af[0] = *(const u32*)&As[rr  ][ks+cp  ];
                af[1] = *(const u32*)&As[rr+8][ks+cp  ];
                af[2] = *(const u32*)&As[rr  ][ks+cp+8];
                af[3] = *(const u32*)&As[rr+8][ks+cp+8];
#pragma unroll
                for (int nt = 0; nt < 8; nt++){
                    u32 bf2[2];
                    int nn = nt*8 + r;
                    bf2[0] = *(const u32*)&Bs[nn][ks+cp  ];
                    bf2[1] = *(const u32*)&Bs[nn][ks+cp+8];
                    mma_bf16(acc[nt], af, bf2);
                }
            }
            int crow = warp*16 + r;
#pragma unroll
            for (int nt = 0; nt < 8; nt++){
                int n = nt*8 + cp;
                *(u32*)(Op + (size_t)crow*4096 + n)     = pk2(acc[nt][0], acc[nt][1]);
                *(u32*)(Op + (size_t)(crow+8)*4096 + n) = pk2(acc[nt][2], acc[nt][3]);
            }
        }
    }
}

// -------- merge: agg = aggR + transpose(aggC) (bf16) --------
__global__ __launch_bounds__(256) void k_merge(){
    int plane = blockIdx.x, which = blockIdx.y, t = threadIdx.x;
    const us16* aR = (which ? g_aggR1 : g_aggR2) + (size_t)plane*4096;
    const us16* aC = (which ? g_aggC1 : g_aggC2) + (size_t)plane*4096;
    us16*       o  = (which ? g_agg1  : g_agg2 ) + (size_t)plane*4096;
    __shared__ us16 sm[64][65];
#pragma unroll
    for (int j = 0; j < 16; j++){
        int idx = j*256 + t;
        sm[idx>>6][idx&63] = aC[idx];
    }
    __syncthreads();
#pragma unroll
    for (int j = 0; j < 16; j++){
        int idx = j*256 + t;
        o[idx] = f2b(b2f(aR[idx]) + b2f(sm[idx&63][idx>>6]));
    }
}

// ------------------------- launch -------------------------
extern "C" void kernel_launch(void* const* d_in, const int* in_sizes, int n_in,
                              void* d_out, int out_size){
    const float* x2    = (const float*)d_in[0];
    const float* x1    = (const float*)d_in[1];
    const float* q_w   = (const float*)d_in[2];
    const float* q_b   = (const float*)d_in[3];
    const float* k_w   = (const float*)d_in[4];
    const float* k_b   = (const float*)d_in[5];
    const float* v_w   = (const float*)d_in[6];
    const float* v_b   = (const float*)d_in[7];
    const float* gamma = (const float*)d_in[8];
    float* out = (float*)d_out;

    k_conv_tr<<<dim3(NB*NC, 2), 256>>>(x2, x1);
    k_conv_w<<<1280, 256>>>(q_w, k_w, v_w);
    k_gemm<<<dim3(32, 1, NB), 256>>>(0, 0, q_b, k_b, nullptr, nullptr, nullptr);
    k_tr_qk<<<dim3(NB*NQ, 2), 256>>>();
    k_energy<<<dim3(64, NB, 2), 256>>>();
    k_softmax<<<NB*4096/8, 256>>>();
    k_agg<<<dim3(64, NB, 2), 256>>>();
    k_merge<<<dim3(NB*NC, 2), 256>>>();
    k_gemm<<<dim3(32, 4, NB), 256>>>(1, 0, v_b, nullptr, x2, gamma, out);
    k_gemm<<<dim3(32, 4, NB), 256>>>(1, 1, v_b, nullptr, x1, gamma, out + (size_t)BCHW);
}

// round 5
// speedup vs baseline: 1.0719x; 1.0719x over previous
#include <cuda_runtime.h>
#include <cuda_bf16.h>

typedef unsigned int u32;
typedef unsigned short us16;

#define NB 8
#define NC 512
#define NQ 64
#define NHW 4096
#define BCHW (NB*NC*NHW)
#define BQHW (NB*NQ*NHW)
#define CHW  (NC*NHW)
#define QHW  (NQ*NHW)

// ------------------------- device scratch -------------------------
__device__ __align__(16) us16  g_x2b [BCHW];
__device__ __align__(16) us16  g_x1b [BCHW];
__device__ __align__(16) us16  g_xT2 [BCHW];
__device__ __align__(16) us16  g_xT1 [BCHW];
__device__ __align__(16) float g_q   [BQHW];
__device__ __align__(16) float g_k   [BQHW];
__device__ __align__(16) float g_qT  [BQHW];
__device__ __align__(16) float g_kT  [BQHW];
__device__ __align__(16) float g_att [NB*NHW*128];
__device__ __align__(16) us16  g_attb[NB*NHW*128];
__device__ __align__(16) us16  g_aggR2[BCHW];
__device__ __align__(16) us16  g_aggC2[BCHW];
__device__ __align__(16) us16  g_aggR1[BCHW];
__device__ __align__(16) us16  g_aggC1[BCHW];
__device__ __align__(16) us16  g_agg2[BCHW];
__device__ __align__(16) us16  g_agg1[BCHW];
__device__ __align__(16) us16  g_wqk[128*NC];
__device__ __align__(16) us16  g_wv [NC*NC];

// ------------------------- helpers -------------------------
__device__ __forceinline__ us16 f2b(float f){
    __nv_bfloat16 h = __float2bfloat16(f);
    return *reinterpret_cast<us16*>(&h);
}
__device__ __forceinline__ float b2f(us16 u){
    __nv_bfloat16 h; *reinterpret_cast<us16*>(&h) = u;
    return __bfloat162float(h);
}
__device__ __forceinline__ u32 pk2(float a, float b){
    return (u32)f2b(a) | ((u32)f2b(b) << 16);
}
__device__ __forceinline__ void mma_bf16(float* d, const u32* a, const u32* b){
    asm volatile(
        "mma.sync.aligned.m16n8k16.row.col.f32.bf16.bf16.f32 "
        "{%0,%1,%2,%3}, {%4,%5,%6,%7}, {%8,%9}, {%0,%1,%2,%3};\n"
        : "+f"(d[0]), "+f"(d[1]), "+f"(d[2]), "+f"(d[3])
        : "r"(a[0]), "r"(a[1]), "r"(a[2]), "r"(a[3]), "r"(b[0]), "r"(b[1]));
}
__device__ __forceinline__ void cpa16(void* s, const void* g){
    u32 sa = (u32)__cvta_generic_to_shared(s);
    asm volatile("cp.async.cg.shared.global [%0], [%1], 16;\n" :: "r"(sa), "l"(g));
}

// -------- convert x -> bf16 (normal + transposed hw plane) --------
__global__ __launch_bounds__(256) void k_conv_tr(const float* __restrict__ x2,
                                                 const float* __restrict__ x1){
    int plane = blockIdx.x, which = blockIdx.y, t = threadIdx.x;
    const float* x  = (which ? x1    : x2   ) + (size_t)plane * 4096;
    us16*       on  = (which ? g_x1b : g_x2b) + (size_t)plane * 4096;
    us16*       ot  = (which ? g_xT1 : g_xT2) + (size_t)plane * 4096;
    __shared__ float sm[64][65];
#pragma unroll
    for (int j = 0; j < 16; j++){
        int idx = j*256 + t;
        float v = x[idx];
        sm[idx>>6][idx&63] = v;
        on[idx] = f2b(v);
    }
    __syncthreads();
#pragma unroll
    for (int j = 0; j < 16; j++){
        int idx = j*256 + t;
        ot[idx] = f2b(sm[idx&63][idx>>6]);
    }
}

// -------- convert weights --------
__global__ __launch_bounds__(256) void k_conv_w(const float* __restrict__ qw,
                                                const float* __restrict__ kw,
                                                const float* __restrict__ vw){
    int i = blockIdx.x * 256 + threadIdx.x;
    if (i < 128 * NC){
        int o = i >> 9, c = i & 511;
        g_wqk[i] = f2b(o < 64 ? qw[o*NC + c] : kw[(o-64)*NC + c]);
    } else if (i < 128*NC + NC*NC){
        int j = i - 128*NC;
        g_wv[j] = f2b(vw[j]);
    }
}

// -------- main bf16 GEMM, cp.async 2-stage pipeline, 128x128 tile, K=512 --------
// grid: (mblocks, 32, z). mode 0: z=b, B=x2b, out q/k(+bias).
// mode 1: z=(b<<1)|sel, B=agg{2,1}, out = gamma*(acc+v_b) + x{2,1}.
__global__ __launch_bounds__(256) void k_gemm(int mode,
    const float* __restrict__ bias0, const float* __restrict__ bias1,
    const float* __restrict__ x2r, const float* __restrict__ x1r,
    const float* __restrict__ gam, float* __restrict__ out)
{
    __shared__ __align__(16) us16 As[2][128][56];   // [m][k], 112B rows
    __shared__ __align__(16) us16 Bs[2][32][136];   // [k][n], 272B rows
    int t = threadIdx.x;
    int m0 = blockIdx.x * 128, n0 = blockIdx.y * 128;
    int b, sel;
    if (mode){ b = blockIdx.z >> 1; sel = blockIdx.z & 1; }
    else     { b = blockIdx.z;      sel = 0; }
    const us16* A  = mode ? g_wv : g_wqk;
    const us16* Bp = (mode ? (sel ? g_agg1 : g_agg2) : g_x2b) + (size_t)b * CHW;

    int warp = t >> 5, lane = t & 31;
    int wm = warp >> 2, wn = warp & 3;           // 2x4 warps -> 64x32 each
    int r = lane >> 2, cp = (lane & 3) * 2;

    // per-thread load coords (2 chunks of 16B each for A and B per tile)
    int ar0 = t >> 2,        ac0 = (t & 3) * 8;
    int ar1 = (t+256) >> 2,  ac1 = ((t+256) & 3) * 8;
    int bk0 = t >> 4,        bn0 = (t & 15) * 8;
    int bk1 = (t+256) >> 4,  bn1 = ((t+256) & 15) * 8;

    float acc[4][4][4];
#pragma unroll
    for (int i = 0; i < 4; i++)
#pragma unroll
        for (int j = 0; j < 4; j++)
#pragma unroll
            for (int q2 = 0; q2 < 4; q2++) acc[i][j][q2] = 0.f;

    // prologue: tile 0 -> stage 0
    {
        cpa16(&As[0][ar0][ac0], A + (size_t)(m0+ar0)*NC + ac0);
        cpa16(&As[0][ar1][ac1], A + (size_t)(m0+ar1)*NC + ac1);
        cpa16(&Bs[0][bk0][bn0], Bp + (size_t)bk0*NHW + n0 + bn0);
        cpa16(&Bs[0][bk1][bn1], Bp + (size_t)bk1*NHW + n0 + bn1);
        asm volatile("cp.async.commit_group;\n");
    }

    for (int kt = 0; kt < 16; kt++){
        int cur = kt & 1;
        if (kt < 15){
            int k0 = (kt+1) * 32;
            int nx = cur ^ 1;
            cpa16(&As[nx][ar0][ac0], A + (size_t)(m0+ar0)*NC + k0 + ac0);
            cpa16(&As[nx][ar1][ac1], A + (size_t)(m0+ar1)*NC + k0 + ac1);
            cpa16(&Bs[nx][bk0][bn0], Bp + (size_t)(k0+bk0)*NHW + n0 + bn0);
            cpa16(&Bs[nx][bk1][bn1], Bp + (size_t)(k0+bk1)*NHW + n0 + bn1);
            asm volatile("cp.async.commit_group;\n");
            asm volatile("cp.async.wait_group 1;\n");
        } else {
            asm volatile("cp.async.wait_group 0;\n");
        }
        __syncthreads();
#pragma unroll
        for (int ks = 0; ks < 32; ks += 16){
            u32 af[4][4], bfr[4][2];
#pragma unroll
            for (int mi = 0; mi < 4; mi++){
                int rr = wm*64 + mi*16 + r;
                af[mi][0] = *(const u32*)&As[cur][rr  ][ks+cp  ];
                af[mi][1] = *(const u32*)&As[cur][rr+8][ks+cp  ];
                af[mi][2] = *(const u32*)&As[cur][rr  ][ks+cp+8];
                af[mi][3] = *(const u32*)&As[cur][rr+8][ks+cp+8];
            }
#pragma unroll
            for (int ni = 0; ni < 4; ni++){
                u32 sa = (u32)__cvta_generic_to_shared(&Bs[cur][ks + (lane & 15)][wn*32 + ni*8]);
                asm volatile("ldmatrix.sync.aligned.m8n8.x2.trans.shared.b16 {%0,%1}, [%2];"
                             : "=r"(bfr[ni][0]), "=r"(bfr[ni][1]) : "r"(sa));
            }
#pragma unroll
            for (int mi = 0; mi < 4; mi++)
#pragma unroll
                for (int ni = 0; ni < 4; ni++)
                    mma_bf16(acc[mi][ni], af[mi], bfr[ni]);
        }
        __syncthreads();
    }

    float gval = mode ? gam[0] : 0.f;
    const float* xres = sel ? x1r : x2r;
    float* outp = mode ? (out + (size_t)sel * BCHW) : out;
#pragma unroll
    for (int mi = 0; mi < 4; mi++){
#pragma unroll
        for (int ni = 0; ni < 4; ni++){
            int ng = n0 + wn*32 + ni*8 + cp;
#pragma unroll
            for (int rr2 = 0; rr2 < 2; rr2++){
                int oo = m0 + wm*64 + mi*16 + r + rr2*8;
                float a0 = acc[mi][ni][rr2*2 + 0];
                float a1 = acc[mi][ni][rr2*2 + 1];
                if (mode == 0){
                    if (oo < 64){
                        float bb = bias0[oo];
                        *(float2*)&g_q[(size_t)(b*NQ + oo)*NHW + ng] = make_float2(a0+bb, a1+bb);
                    } else {
                        float bb = bias1[oo-64];
                        *(float2*)&g_k[(size_t)(b*NQ + oo-64)*NHW + ng] = make_float2(a0+bb, a1+bb);
                    }
                } else {
                    float bb = bias0[oo];
                    size_t oi = (size_t)(b*NC + oo)*NHW + ng;
                    float2 xr = *(const float2*)(xres + oi);
                    *(float2*)(outp + oi) = make_float2(gval*(a0+bb)+xr.x, gval*(a1+bb)+xr.y);
                }
            }
        }
    }
}

// -------- q,k fp32 plane transpose: [h][w] -> [w][h] --------
__global__ __launch_bounds__(256) void k_tr_qk(){
    int p = blockIdx.x, which = blockIdx.y, t = threadIdx.x;
    const float* src = (which ? g_k  : g_q ) + (size_t)p*4096;
    float*       dst = (which ? g_kT : g_qT) + (size_t)p*4096;
    __shared__ float sm[64][65];
#pragma unroll
    for (int j = 0; j < 16; j++){
        int idx = j*256 + t;
        sm[idx>>6][idx&63] = src[idx];
    }
    __syncthreads();
#pragma unroll
    for (int j = 0; j < 16; j++){
        int idx = j*256 + t;
        dst[idx] = sm[idx&63][idx>>6];
    }
}

// -------- energies (fp32): dir0 = H (uses qT/kT, fixed w), dir1 = W (fixed h) --------
__global__ __launch_bounds__(256) void k_energy(){
    __shared__ float Qs[64][68], Ks[64][68];
    int plane = blockIdx.x, b = blockIdx.y, dir = blockIdx.z, t = threadIdx.x;
    const float* qb = (dir ? g_q : g_qT) + (size_t)b*QHW + plane*64;
    const float* kb = (dir ? g_k : g_kT) + (size_t)b*QHW + plane*64;
#pragma unroll
    for (int j = 0; j < 16; j++){
        int idx = j*256 + t;
        int cq = idx >> 6, i = idx & 63;
        Qs[cq][i] = qb[(size_t)cq*4096 + i];
        Ks[cq][i] = kb[(size_t)cq*4096 + i];
    }
    __syncthreads();
    int i = t >> 2, j0 = (t & 3) * 16;
    float acc[16];
#pragma unroll
    for (int u = 0; u < 16; u++) acc[u] = 0.f;
    for (int cq = 0; cq < 64; cq++){
        float qv = Qs[cq][i];
#pragma unroll
        for (int u4 = 0; u4 < 4; u4++){
            float4 kv = *(const float4*)&Ks[cq][j0 + u4*4];
            acc[u4*4+0] += qv * kv.x;
            acc[u4*4+1] += qv * kv.y;
            acc[u4*4+2] += qv * kv.z;
            acc[u4*4+3] += qv * kv.w;
        }
    }
    size_t pix; int joff;
    if (dir == 0){ pix = (size_t)b*4096 + (size_t)i*64 + plane;   joff = 0;  }
    else         { pix = (size_t)b*4096 + (size_t)plane*64 + i;   joff = 64; }
    float* dst = g_att + pix*128 + joff + j0;
#pragma unroll
    for (int u4 = 0; u4 < 4; u4++)
        *(float4*)(dst + u4*4) = make_float4(acc[u4*4], acc[u4*4+1], acc[u4*4+2], acc[u4*4+3]);
}

// -------- softmax over 128, write bf16 --------
__global__ __launch_bounds__(256) void k_softmax(){
    int t = threadIdx.x;
    size_t pix = (size_t)blockIdx.x*8 + (t>>5);
    int lane = t & 31;
    float4 v = *(const float4*)(g_att + pix*128 + lane*4);
    float m = fmaxf(fmaxf(v.x, v.y), fmaxf(v.z, v.w));
#pragma unroll
    for (int o = 16; o; o >>= 1) m = fmaxf(m, __shfl_xor_sync(0xffffffffu, m, o));
    float e0 = __expf(v.x - m), e1 = __expf(v.y - m);
    float e2 = __expf(v.z - m), e3 = __expf(v.w - m);
    float s = e0 + e1 + e2 + e3;
#pragma unroll
    for (int o = 16; o; o >>= 1) s += __shfl_xor_sync(0xffffffffu, s, o);
    float inv = 1.f / s;
    u32 lo = pk2(e0*inv, e1*inv), hi = pk2(e2*inv, e3*inv);
    *(uint2*)(g_attb + pix*128 + lane*4) = make_uint2(lo, hi);
}

// -------- aggregation: agg[c][n] = sum_j X[c][j] * att[n][j] (bf16 mma) --------
__global__ __launch_bounds__(256) void k_agg(){
    __shared__ __align__(16) us16 Bs[64][72];    // [n][k]
    __shared__ __align__(16) us16 As[128][72];   // [c][k]
    int plane = blockIdx.x, b = blockIdx.y, dir = blockIdx.z, t = threadIdx.x;
    const us16* X2 = (dir ? g_x2b  : g_xT2 ) + (size_t)b*CHW + plane*64;
    const us16* X1 = (dir ? g_x1b  : g_xT1 ) + (size_t)b*CHW + plane*64;
    us16*       O2 = (dir ? g_aggR2: g_aggC2) + (size_t)b*CHW + plane*64;
    us16*       O1 = (dir ? g_aggR1: g_aggC1) + (size_t)b*CHW + plane*64;
    const us16* attp; int istride;
    if (dir == 0){ attp = g_attb + ((size_t)b*4096 + plane)*128;            istride = 8192; }
    else         { attp = g_attb + ((size_t)b*4096 + (size_t)plane*64)*128 + 64; istride = 128; }

    int warp = t >> 5, lane = t & 31;
    int r = lane >> 2, cp = (lane & 3) * 2;

#pragma unroll
    for (int it = 0; it < 2; it++){
        int job = it*256 + t;
        int i = job >> 3, seg = job & 7;
        *(uint4*)&Bs[i][seg*8] = *(const uint4*)(attp + (size_t)i*istride + seg*8);
    }

    for (int c0 = 0; c0 < NC; c0 += 128){
        for (int tsel = 0; tsel < 2; tsel++){
            const us16* Xp = (tsel ? X1 : X2) + (size_t)c0 * 4096;
            us16*       Op = (tsel ? O1 : O2) + (size_t)c0 * 4096;
            __syncthreads();
#pragma unroll
            for (int it = 0; it < 4; it++){
                int job = it*256 + t;
                int rr = job >> 3, seg = job & 7;
                *(uint4*)&As[rr][seg*8] = *(const uint4*)(Xp + (size_t)rr*4096 + seg*8);
            }
            __syncthreads();
            float acc[8][4];
#pragma unroll
            for (int nt = 0; nt < 8; nt++)
#pragma unroll
                for (int q2 = 0; q2 < 4; q2++) acc[nt][q2] = 0.f;
#pragma unroll
            for (int ks = 0; ks < 64; ks += 16){
                u32 af[4];
                int rr = warp*16 + r;
                af[0] = *(const u32*)&As[rr  ][ks+cp  ];
                af[1] = *(const u32*)&As[rr+8][ks+cp  ];
                af[2] = *(const u32*)&As[rr  ][ks+cp+8];
                af[3] = *(const u32*)&As[rr+8][ks+cp+8];
#pragma unroll
                for (int nt = 0; nt < 8; nt++){
                    u32 bf2[2];
                    int nn = nt*8 + r;
                    bf2[0] = *(const u32*)&Bs[nn][ks+cp  ];
                    bf2[1] = *(const u32*)&Bs[nn][ks+cp+8];
                    mma_bf16(acc[nt], af, bf2);
                }
            }
            int crow = warp*16 + r;
#pragma unroll
            for (int nt = 0; nt < 8; nt++){
                int n = nt*8 + cp;
                *(u32*)(Op + (size_t)crow*4096 + n)     = pk2(acc[nt][0], acc[nt][1]);
                *(u32*)(Op + (size_t)(crow+8)*4096 + n) = pk2(acc[nt][2], acc[nt][3]);
            }
        }
    }
}

// -------- merge: agg = aggR + transpose(aggC) (bf16) --------
__global__ __launch_bounds__(256) void k_merge(){
    int plane = blockIdx.x, which = blockIdx.y, t = threadIdx.x;
    const us16* aR = (which ? g_aggR1 : g_aggR2) + (size_t)plane*4096;
    const us16* aC = (which ? g_aggC1 : g_aggC2) + (size_t)plane*4096;
    us16*       o  = (which ? g_agg1  : g_agg2 ) + (size_t)plane*4096;
    __shared__ us16 sm[64][65];
#pragma unroll
    for (int j = 0; j < 16; j++){
        int idx = j*256 + t;
        sm[idx>>6][idx&63] = aC[idx];
    }
    __syncthreads();
#pragma unroll
    for (int j = 0; j < 16; j++){
        int idx = j*256 + t;
        o[idx] = f2b(b2f(aR[idx]) + b2f(sm[idx&63][idx>>6]));
    }
}

// ------------------------- launch -------------------------
extern "C" void kernel_launch(void* const* d_in, const int* in_sizes, int n_in,
                              void* d_out, int out_size){
    const float* x2    = (const float*)d_in[0];
    const float* x1    = (const float*)d_in[1];
    const float* q_w   = (const float*)d_in[2];
    const float* q_b   = (const float*)d_in[3];
    const float* k_w   = (const float*)d_in[4];
    const float* k_b   = (const float*)d_in[5];
    const float* v_w   = (const float*)d_in[6];
    const float* v_b   = (const float*)d_in[7];
    const float* gamma = (const float*)d_in[8];
    float* out = (float*)d_out;

    k_conv_tr<<<dim3(NB*NC, 2), 256>>>(x2, x1);
    k_conv_w<<<1280, 256>>>(q_w, k_w, v_w);
    k_gemm<<<dim3(1, 32, NB), 256>>>(0, q_b, k_b, nullptr, nullptr, nullptr, nullptr);
    k_tr_qk<<<dim3(NB*NQ, 2), 256>>>();
    k_energy<<<dim3(64, NB, 2), 256>>>();
    k_softmax<<<NB*4096/8, 256>>>();
    k_agg<<<dim3(64, NB, 2), 256>>>();
    k_merge<<<dim3(NB*NC, 2), 256>>>();
    k_gemm<<<dim3(4, 32, 16), 256>>>(1, v_b, nullptr, x2, x1, gamma, out);
}

// round 6
// speedup vs baseline: 1.2405x; 1.1572x over previous
#include <cuda_runtime.h>
#include <cuda_bf16.h>

typedef unsigned int u32;
typedef unsigned short us16;

#define NB 8
#define NC 512
#define NQ 64
#define NHW 4096
#define BCHW (NB*NC*NHW)
#define BQHW (NB*NQ*NHW)
#define CHW  (NC*NHW)
#define QHW  (NQ*NHW)

// ------------------------- device scratch -------------------------
__device__ __align__(16) us16  g_x2b [BCHW];
__device__ __align__(16) us16  g_x1b [BCHW];
__device__ __align__(16) us16  g_xT2 [BCHW];
__device__ __align__(16) us16  g_xT1 [BCHW];
__device__ __align__(16) float g_q   [BQHW];
__device__ __align__(16) float g_k   [BQHW];
__device__ __align__(16) float g_qT  [BQHW];
__device__ __align__(16) float g_kT  [BQHW];
__device__ __align__(16) float g_att [NB*NHW*128];
__device__ __align__(16) us16  g_attb[NB*NHW*128];
__device__ __align__(16) us16  g_aggP[2*BCHW];   // dir0 partial, channel-last [sel][b][pix][c]
__device__ __align__(16) us16  g_aggF[2*BCHW];   // final agg, channel-last
__device__ __align__(16) us16  g_wqk[128*NC];
__device__ __align__(16) us16  g_wv [NC*NC];

// ------------------------- helpers -------------------------
__device__ __forceinline__ us16 f2b(float f){
    __nv_bfloat16 h = __float2bfloat16(f);
    return *reinterpret_cast<us16*>(&h);
}
__device__ __forceinline__ float b2f(us16 u){
    __nv_bfloat16 h; *reinterpret_cast<us16*>(&h) = u;
    return __bfloat162float(h);
}
__device__ __forceinline__ u32 pk2(float a, float b){
    return (u32)f2b(a) | ((u32)f2b(b) << 16);
}
__device__ __forceinline__ u32 addbf2(u32 s, u32 p){
    float lo = b2f((us16)(s & 0xffff)) + b2f((us16)(p & 0xffff));
    float hi = b2f((us16)(s >> 16))    + b2f((us16)(p >> 16));
    return pk2(lo, hi);
}
__device__ __forceinline__ void mma_bf16(float* d, const u32* a, const u32* b){
    asm volatile(
        "mma.sync.aligned.m16n8k16.row.col.f32.bf16.bf16.f32 "
        "{%0,%1,%2,%3}, {%4,%5,%6,%7}, {%8,%9}, {%0,%1,%2,%3};\n"
        : "+f"(d[0]), "+f"(d[1]), "+f"(d[2]), "+f"(d[3])
        : "r"(a[0]), "r"(a[1]), "r"(a[2]), "r"(a[3]), "r"(b[0]), "r"(b[1]));
}
__device__ __forceinline__ void cpa16(void* s, const void* g){
    u32 sa = (u32)__cvta_generic_to_shared(s);
    asm volatile("cp.async.cg.shared.global [%0], [%1], 16;\n" :: "r"(sa), "l"(g));
}

// -------- convert x -> bf16 (normal + transposed hw plane) --------
__global__ __launch_bounds__(256) void k_conv_tr(const float* __restrict__ x2,
                                                 const float* __restrict__ x1){
    int plane = blockIdx.x, which = blockIdx.y, t = threadIdx.x;
    const float* x  = (which ? x1    : x2   ) + (size_t)plane * 4096;
    us16*       on  = (which ? g_x1b : g_x2b) + (size_t)plane * 4096;
    us16*       ot  = (which ? g_xT1 : g_xT2) + (size_t)plane * 4096;
    __shared__ float sm[64][65];
#pragma unroll
    for (int j = 0; j < 16; j++){
        int idx = j*256 + t;
        float v = x[idx];
        sm[idx>>6][idx&63] = v;
        on[idx] = f2b(v);
    }
    __syncthreads();
#pragma unroll
    for (int j = 0; j < 16; j++){
        int idx = j*256 + t;
        ot[idx] = f2b(sm[idx&63][idx>>6]);
    }
}

// -------- convert weights --------
__global__ __launch_bounds__(256) void k_conv_w(const float* __restrict__ qw,
                                                const float* __restrict__ kw,
                                                const float* __restrict__ vw){
    int i = blockIdx.x * 256 + threadIdx.x;
    if (i < 128 * NC){
        int o = i >> 9, c = i & 511;
        g_wqk[i] = f2b(o < 64 ? qw[o*NC + c] : kw[(o-64)*NC + c]);
    } else if (i < 128*NC + NC*NC){
        int j = i - 128*NC;
        g_wv[j] = f2b(vw[j]);
    }
}

// -------- mode-0 GEMM: [q_w;k_w](128x512) * x2b -> q,k (+bias), 2-stage cp.async --------
__global__ __launch_bounds__(256) void k_gemm0(
    const float* __restrict__ bias0, const float* __restrict__ bias1)
{
    __shared__ __align__(16) us16 As[2][128][56];
    __shared__ __align__(16) us16 Bs[2][32][136];
    int t = threadIdx.x;
    int m0 = 0, n0 = blockIdx.y * 128;
    int b = blockIdx.z;
    const us16* A  = g_wqk;
    const us16* Bp = g_x2b + (size_t)b * CHW;

    int warp = t >> 5, lane = t & 31;
    int wm = warp >> 2, wn = warp & 3;
    int r = lane >> 2, cp = (lane & 3) * 2;

    int ar0 = t >> 2,        ac0 = (t & 3) * 8;
    int ar1 = (t+256) >> 2,  ac1 = ((t+256) & 3) * 8;
    int bk0 = t >> 4,        bn0 = (t & 15) * 8;
    int bk1 = (t+256) >> 4,  bn1 = ((t+256) & 15) * 8;

    float acc[4][4][4];
#pragma unroll
    for (int i = 0; i < 4; i++)
#pragma unroll
        for (int j = 0; j < 4; j++)
#pragma unroll
            for (int q2 = 0; q2 < 4; q2++) acc[i][j][q2] = 0.f;

    cpa16(&As[0][ar0][ac0], A + (size_t)(m0+ar0)*NC + ac0);
    cpa16(&As[0][ar1][ac1], A + (size_t)(m0+ar1)*NC + ac1);
    cpa16(&Bs[0][bk0][bn0], Bp + (size_t)bk0*NHW + n0 + bn0);
    cpa16(&Bs[0][bk1][bn1], Bp + (size_t)bk1*NHW + n0 + bn1);
    asm volatile("cp.async.commit_group;\n");

    for (int kt = 0; kt < 16; kt++){
        int cur = kt & 1;
        if (kt < 15){
            int k0 = (kt+1) * 32;
            int nx = cur ^ 1;
            cpa16(&As[nx][ar0][ac0], A + (size_t)(m0+ar0)*NC + k0 + ac0);
            cpa16(&As[nx][ar1][ac1], A + (size_t)(m0+ar1)*NC + k0 + ac1);
            cpa16(&Bs[nx][bk0][bn0], Bp + (size_t)(k0+bk0)*NHW + n0 + bn0);
            cpa16(&Bs[nx][bk1][bn1], Bp + (size_t)(k0+bk1)*NHW + n0 + bn1);
            asm volatile("cp.async.commit_group;\n");
            asm volatile("cp.async.wait_group 1;\n");
        } else {
            asm volatile("cp.async.wait_group 0;\n");
        }
        __syncthreads();
#pragma unroll
        for (int ks = 0; ks < 32; ks += 16){
            u32 af[4][4], bfr[4][2];
#pragma unroll
            for (int mi = 0; mi < 4; mi++){
                int rr = wm*64 + mi*16 + r;
                af[mi][0] = *(const u32*)&As[cur][rr  ][ks+cp  ];
                af[mi][1] = *(const u32*)&As[cur][rr+8][ks+cp  ];
                af[mi][2] = *(const u32*)&As[cur][rr  ][ks+cp+8];
                af[mi][3] = *(const u32*)&As[cur][rr+8][ks+cp+8];
            }
#pragma unroll
            for (int ni = 0; ni < 4; ni++){
                u32 sa = (u32)__cvta_generic_to_shared(&Bs[cur][ks + (lane & 15)][wn*32 + ni*8]);
                asm volatile("ldmatrix.sync.aligned.m8n8.x2.trans.shared.b16 {%0,%1}, [%2];"
                             : "=r"(bfr[ni][0]), "=r"(bfr[ni][1]) : "r"(sa));
            }
#pragma unroll
            for (int mi = 0; mi < 4; mi++)
#pragma unroll
                for (int ni = 0; ni < 4; ni++)
                    mma_bf16(acc[mi][ni], af[mi], bfr[ni]);
        }
        __syncthreads();
    }

#pragma unroll
    for (int mi = 0; mi < 4; mi++){
#pragma unroll
        for (int ni = 0; ni < 4; ni++){
            int ng = n0 + wn*32 + ni*8 + cp;
#pragma unroll
            for (int rr2 = 0; rr2 < 2; rr2++){
                int oo = wm*64 + mi*16 + r + rr2*8;
                float a0 = acc[mi][ni][rr2*2 + 0];
                float a1 = acc[mi][ni][rr2*2 + 1];
                if (oo < 64){
                    float bb = bias0[oo];
                    *(float2*)&g_q[(size_t)(b*NQ + oo)*NHW + ng] = make_float2(a0+bb, a1+bb);
                } else {
                    float bb = bias1[oo-64];
                    *(float2*)&g_k[(size_t)(b*NQ + oo-64)*NHW + ng] = make_float2(a0+bb, a1+bb);
                }
            }
        }
    }
}

// -------- q,k fp32 plane transpose --------
__global__ __launch_bounds__(256) void k_tr_qk(){
    int p = blockIdx.x, which = blockIdx.y, t = threadIdx.x;
    const float* src = (which ? g_k  : g_q ) + (size_t)p*4096;
    float*       dst = (which ? g_kT : g_qT) + (size_t)p*4096;
    __shared__ float sm[64][65];
#pragma unroll
    for (int j = 0; j < 16; j++){
        int idx = j*256 + t;
        sm[idx>>6][idx&63] = src[idx];
    }
    __syncthreads();
#pragma unroll
    for (int j = 0; j < 16; j++){
        int idx = j*256 + t;
        dst[idx] = sm[idx&63][idx>>6];
    }
}

// -------- energies (fp32) --------
__global__ __launch_bounds__(256) void k_energy(){
    __shared__ float Qs[64][68], Ks[64][68];
    int plane = blockIdx.x, b = blockIdx.y, dir = blockIdx.z, t = threadIdx.x;
    const float* qb = (dir ? g_q : g_qT) + (size_t)b*QHW + plane*64;
    const float* kb = (dir ? g_k : g_kT) + (size_t)b*QHW + plane*64;
#pragma unroll
    for (int j = 0; j < 16; j++){
        int idx = j*256 + t;
        int cq = idx >> 6, i = idx & 63;
        Qs[cq][i] = qb[(size_t)cq*4096 + i];
        Ks[cq][i] = kb[(size_t)cq*4096 + i];
    }
    __syncthreads();
    int i = t >> 2, j0 = (t & 3) * 16;
    float acc[16];
#pragma unroll
    for (int u = 0; u < 16; u++) acc[u] = 0.f;
    for (int cq = 0; cq < 64; cq++){
        float qv = Qs[cq][i];
#pragma unroll
        for (int u4 = 0; u4 < 4; u4++){
            float4 kv = *(const float4*)&Ks[cq][j0 + u4*4];
            acc[u4*4+0] += qv * kv.x;
            acc[u4*4+1] += qv * kv.y;
            acc[u4*4+2] += qv * kv.z;
            acc[u4*4+3] += qv * kv.w;
        }
    }
    size_t pix; int joff;
    if (dir == 0){ pix = (size_t)b*4096 + (size_t)i*64 + plane;   joff = 0;  }
    else         { pix = (size_t)b*4096 + (size_t)plane*64 + i;   joff = 64; }
    float* dst = g_att + pix*128 + joff + j0;
#pragma unroll
    for (int u4 = 0; u4 < 4; u4++)
        *(float4*)(dst + u4*4) = make_float4(acc[u4*4], acc[u4*4+1], acc[u4*4+2], acc[u4*4+3]);
}

// -------- softmax over 128, write bf16 --------
__global__ __launch_bounds__(256) void k_softmax(){
    int t = threadIdx.x;
    size_t pix = (size_t)blockIdx.x*8 + (t>>5);
    int lane = t & 31;
    float4 v = *(const float4*)(g_att + pix*128 + lane*4);
    float m = fmaxf(fmaxf(v.x, v.y), fmaxf(v.z, v.w));
#pragma unroll
    for (int o = 16; o; o >>= 1) m = fmaxf(m, __shfl_xor_sync(0xffffffffu, m, o));
    float e0 = __expf(v.x - m), e1 = __expf(v.y - m);
    float e2 = __expf(v.z - m), e3 = __expf(v.w - m);
    float s = e0 + e1 + e2 + e3;
#pragma unroll
    for (int o = 16; o; o >>= 1) s += __shfl_xor_sync(0xffffffffu, s, o);
    float inv = 1.f / s;
    u32 lo = pk2(e0*inv, e1*inv), hi = pk2(e2*inv, e3*inv);
    *(uint2*)(g_attb + pix*128 + lane*4) = make_uint2(lo, hi);
}

// -------- aggregation (channel-last out), cp.async pipelined, dir1 fuses merge --------
// agg[c][n] = sum_j X[c][j] * att[n][j]; out stored [pixel][c].
__global__ __launch_bounds__(256) void k_agg(int dir){
    __shared__ __align__(16) us16 Bs[64][72];
    __shared__ __align__(16) us16 As[2][128][72];
    int plane = blockIdx.x, b = blockIdx.y, t = threadIdx.x;
    const us16* X2 = (dir ? g_x2b : g_xT2) + (size_t)b*CHW + plane*64;
    const us16* X1 = (dir ? g_x1b : g_xT1) + (size_t)b*CHW + plane*64;
    const us16* attp; int istride;
    if (dir == 0){ attp = g_attb + ((size_t)b*4096 + plane)*128;                 istride = 8192; }
    else         { attp = g_attb + ((size_t)b*4096 + (size_t)plane*64)*128 + 64; istride = 128;  }

    int warp = t >> 5, lane = t & 31;
    int r = lane >> 5 ? 0 : (lane >> 2), cp = (lane & 3) * 2;
    r = lane >> 2;

    // issue cp.async for iteration i into stage st
    // iteration i: c0 = (i>>1)*128, tsel = i&1
    {
        const us16* Xp = X2;  // iter 0: c0=0, tsel=0
#pragma unroll
        for (int it = 0; it < 4; it++){
            int job = it*256 + t;
            int rr = job >> 3, seg = (job & 7) * 8;
            cpa16(&As[0][rr][seg], Xp + (size_t)rr*4096 + seg);
        }
        asm volatile("cp.async.commit_group;\n");
    }
#pragma unroll
    for (int it = 0; it < 2; it++){
        int job = it*256 + t;
        int i2 = job >> 3, seg = (job & 7) * 8;
        *(uint4*)&Bs[i2][seg] = *(const uint4*)(attp + (size_t)i2*istride + seg);
    }

    for (int i = 0; i < 8; i++){
        int cur = i & 1;
        if (i < 7){
            int c0n = ((i+1) >> 1) * 128, tseln = (i+1) & 1;
            const us16* Xp = (tseln ? X1 : X2) + (size_t)c0n * 4096;
            int nx = cur ^ 1;
#pragma unroll
            for (int it = 0; it < 4; it++){
                int job = it*256 + t;
                int rr = job >> 3, seg = (job & 7) * 8;
                cpa16(&As[nx][rr][seg], Xp + (size_t)rr*4096 + seg);
            }
            asm volatile("cp.async.commit_group;\n");
            asm volatile("cp.async.wait_group 1;\n");
        } else {
            asm volatile("cp.async.wait_group 0;\n");
        }
        __syncthreads();

        float acc[8][4];
#pragma unroll
        for (int nt = 0; nt < 8; nt++)
#pragma unroll
            for (int q2 = 0; q2 < 4; q2++) acc[nt][q2] = 0.f;
#pragma unroll
        for (int ks = 0; ks < 64; ks += 16){
            u32 af[4];
            int rr = warp*16 + r;
            af[0] = *(const u32*)&As[cur][rr  ][ks+cp  ];
            af[1] = *(const u32*)&As[cur][rr+8][ks+cp  ];
            af[2] = *(const u32*)&As[cur][rr  ][ks+cp+8];
            af[3] = *(const u32*)&As[cur][rr+8][ks+cp+8];
#pragma unroll
            for (int nt = 0; nt < 8; nt++){
                u32 bf2[2];
                int nn = nt*8 + r;
                bf2[0] = *(const u32*)&Bs[nn][ks+cp  ];
                bf2[1] = *(const u32*)&Bs[nn][ks+cp+8];
                mma_bf16(acc[nt], af, bf2);
            }
        }
        __syncthreads();           // all warps done reading As[cur]

        // stage transpose into As[cur] region as stg[64 n][136 c-stride]
        us16* stg = &As[cur][0][0];
        int crow = warp*16 + r;
#pragma unroll
        for (int nt = 0; nt < 8; nt++){
            int n = nt*8 + cp;
            stg[n*136 + crow]         = f2b(acc[nt][0]);
            stg[(n+1)*136 + crow]     = f2b(acc[nt][1]);
            stg[n*136 + crow + 8]     = f2b(acc[nt][2]);
            stg[(n+1)*136 + crow + 8] = f2b(acc[nt][3]);
        }
        __syncthreads();

        // coalesced channel-last write (dir1: add dir0 partial)
        int c0 = (i >> 1) * 128, tsel = i & 1;
        us16* dP = g_aggP + (size_t)tsel*BCHW + (size_t)b*CHW;
        us16* dF = g_aggF + (size_t)tsel*BCHW + (size_t)b*CHW;
#pragma unroll
        for (int it = 0; it < 4; it++){
            int job = it*256 + t;
            int n = job >> 4, cseg = (job & 15) * 8;
            uint4 s = *(uint4*)&stg[n*136 + cseg];
            size_t pix = dir ? ((size_t)plane*64 + n) : ((size_t)n*64 + plane);
            size_t off = pix*512 + c0 + cseg;
            if (dir == 0){
                *(uint4*)(dP + off) = s;
            } else {
                uint4 p = *(const uint4*)(dP + off);
                uint4 o4;
                o4.x = addbf2(s.x, p.x); o4.y = addbf2(s.y, p.y);
                o4.z = addbf2(s.z, p.z); o4.w = addbf2(s.w, p.w);
                *(uint4*)(dF + off) = o4;
            }
        }
        __syncthreads();           // stg reads done before next cp into this stage
    }
}

// -------- output conv GEMM: v_w(512x512) * aggF(channel-last) + epilogue --------
__global__ __launch_bounds__(256) void k_gemm1(
    const float* __restrict__ vb, const float* __restrict__ x2r,
    const float* __restrict__ x1r, const float* __restrict__ gam,
    float* __restrict__ out)
{
    __shared__ __align__(16) us16 As[2][128][40];   // [m][k]
    __shared__ __align__(16) us16 Bs[2][128][40];   // [n][k]
    int t = threadIdx.x;
    int m0 = blockIdx.x * 128, n0 = blockIdx.y * 128;
    int b = blockIdx.z >> 1, sel = blockIdx.z & 1;
    const us16* A  = g_wv;
    const us16* Bp = g_aggF + (size_t)sel*BCHW + (size_t)b*CHW;   // [pixel][c]

    int warp = t >> 5, lane = t & 31;
    int wm = warp >> 2, wn = warp & 3;
    int r = lane >> 2, cp = (lane & 3) * 2;

    int lr = t >> 2, lc = (t & 3) * 8;   // rows 0..63 (t<256), +64 for second chunk

    float acc[4][4][4];
#pragma unroll
    for (int i = 0; i < 4; i++)
#pragma unroll
        for (int j = 0; j < 4; j++)
#pragma unroll
            for (int q2 = 0; q2 < 4; q2++) acc[i][j][q2] = 0.f;

    cpa16(&As[0][lr   ][lc], A  + (size_t)(m0+lr   )*NC  + lc);
    cpa16(&As[0][lr+64][lc], A  + (size_t)(m0+lr+64)*NC  + lc);
    cpa16(&Bs[0][lr   ][lc], Bp + (size_t)(n0+lr   )*512 + lc);
    cpa16(&Bs[0][lr+64][lc], Bp + (size_t)(n0+lr+64)*512 + lc);
    asm volatile("cp.async.commit_group;\n");

    for (int kt = 0; kt < 16; kt++){
        int cur = kt & 1;
        if (kt < 15){
            int k0 = (kt+1) * 32;
            int nx = cur ^ 1;
            cpa16(&As[nx][lr   ][lc], A  + (size_t)(m0+lr   )*NC  + k0 + lc);
            cpa16(&As[nx][lr+64][lc], A  + (size_t)(m0+lr+64)*NC  + k0 + lc);
            cpa16(&Bs[nx][lr   ][lc], Bp + (size_t)(n0+lr   )*512 + k0 + lc);
            cpa16(&Bs[nx][lr+64][lc], Bp + (size_t)(n0+lr+64)*512 + k0 + lc);
            asm volatile("cp.async.commit_group;\n");
            asm volatile("cp.async.wait_group 1;\n");
        } else {
            asm volatile("cp.async.wait_group 0;\n");
        }
        __syncthreads();
#pragma unroll
        for (int ks = 0; ks < 32; ks += 16){
            u32 af[4][4], bfr[4][2];
#pragma unroll
            for (int mi = 0; mi < 4; mi++){
                int rr = wm*64 + mi*16 + r;
                af[mi][0] = *(const u32*)&As[cur][rr  ][ks+cp  ];
                af[mi][1] = *(const u32*)&As[cur][rr+8][ks+cp  ];
                af[mi][2] = *(const u32*)&As[cur][rr  ][ks+cp+8];
                af[mi][3] = *(const u32*)&As[cur][rr+8][ks+cp+8];
            }
#pragma unroll
            for (int ni = 0; ni < 4; ni++){
                int nn = wn*32 + ni*8 + r;
                bfr[ni][0] = *(const u32*)&Bs[cur][nn][ks+cp  ];
                bfr[ni][1] = *(const u32*)&Bs[cur][nn][ks+cp+8];
            }
#pragma unroll
            for (int mi = 0; mi < 4; mi++)
#pragma unroll
                for (int ni = 0; ni < 4; ni++)
                    mma_bf16(acc[mi][ni], af[mi], bfr[ni]);
        }
        __syncthreads();
    }

    float gval = gam[0];
    const float* xres = sel ? x1r : x2r;
    float* outp = out + (size_t)sel * BCHW;
#pragma unroll
    for (int mi = 0; mi < 4; mi++){
#pragma unroll
        for (int ni = 0; ni < 4; ni++){
            int ng = n0 + wn*32 + ni*8 + cp;
#pragma unroll
            for (int rr2 = 0; rr2 < 2; rr2++){
                int oo = m0 + wm*64 + mi*16 + r + rr2*8;
                float a0 = acc[mi][ni][rr2*2 + 0];
                float a1 = acc[mi][ni][rr2*2 + 1];
                float bb = vb[oo];
                size_t oi = (size_t)(b*NC + oo)*NHW + ng;
                float2 xr = *(const float2*)(xres + oi);
                *(float2*)(outp + oi) = make_float2(gval*(a0+bb)+xr.x, gval*(a1+bb)+xr.y);
            }
        }
    }
}

// ------------------------- launch -------------------------
extern "C" void kernel_launch(void* const* d_in, const int* in_sizes, int n_in,
                              void* d_out, int out_size){
    const float* x2    = (const float*)d_in[0];
    const float* x1    = (const float*)d_in[1];
    const float* q_w   = (const float*)d_in[2];
    const float* q_b   = (const float*)d_in[3];
    const float* k_w   = (const float*)d_in[4];
    const float* k_b   = (const float*)d_in[5];
    const float* v_w   = (const float*)d_in[6];
    const float* v_b   = (const float*)d_in[7];
    const float* gamma = (const float*)d_in[8];
    float* out = (float*)d_out;

    k_conv_tr<<<dim3(NB*NC, 2), 256>>>(x2, x1);
    k_conv_w<<<1280, 256>>>(q_w, k_w, v_w);
    k_gemm0<<<dim3(1, 32, NB), 256>>>(q_b, k_b);
    k_tr_qk<<<dim3(NB*NQ, 2), 256>>>();
    k_energy<<<dim3(64, NB, 2), 256>>>();
    k_softmax<<<NB*4096/8, 256>>>();
    k_agg<<<dim3(64, NB), 256>>>(0);
    k_agg<<<dim3(64, NB), 256>>>(1);
    k_gemm1<<<dim3(4, 32, 16), 256>>>(v_b, x2, x1, gamma, out);
}

// round 7
// speedup vs baseline: 1.4909x; 1.2018x over previous
#include <cuda_runtime.h>
#include <cuda_bf16.h>

typedef unsigned int u32;
typedef unsigned short us16;

#define NB 8
#define NC 512
#define NQ 64
#define NHW 4096
#define BCHW (NB*NC*NHW)
#define CHW  (NC*NHW)

// ------------------------- device scratch -------------------------
__device__ __align__(16) us16  g_x2b [BCHW];
__device__ __align__(16) us16  g_x1b [BCHW];
__device__ __align__(16) us16  g_xT2 [BCHW];
__device__ __align__(16) us16  g_xT1 [BCHW];
__device__ __align__(16) us16  g_qkb [NB*NHW*128];   // [b][pix][q0..63,k0..63] bf16
__device__ __align__(16) float g_att [NB*NHW*128];
__device__ __align__(16) us16  g_attb[NB*NHW*128];
__device__ __align__(16) us16  g_aggP[2*BCHW];       // dir0 partial, channel-last
__device__ __align__(16) us16  g_aggF[2*BCHW];       // final agg, channel-last
__device__ __align__(16) us16  g_wqk[128*NC];
__device__ __align__(16) us16  g_wv [NC*NC];

// ------------------------- helpers -------------------------
__device__ __forceinline__ us16 f2b(float f){
    __nv_bfloat16 h = __float2bfloat16(f);
    return *reinterpret_cast<us16*>(&h);
}
__device__ __forceinline__ float b2f(us16 u){
    __nv_bfloat16 h; *reinterpret_cast<us16*>(&h) = u;
    return __bfloat162float(h);
}
__device__ __forceinline__ u32 pk2(float a, float b){
    return (u32)f2b(a) | ((u32)f2b(b) << 16);
}
__device__ __forceinline__ u32 addbf2(u32 s, u32 p){
    float lo = b2f((us16)(s & 0xffff)) + b2f((us16)(p & 0xffff));
    float hi = b2f((us16)(s >> 16))    + b2f((us16)(p >> 16));
    return pk2(lo, hi);
}
__device__ __forceinline__ void mma_bf16(float* d, const u32* a, const u32* b){
    asm volatile(
        "mma.sync.aligned.m16n8k16.row.col.f32.bf16.bf16.f32 "
        "{%0,%1,%2,%3}, {%4,%5,%6,%7}, {%8,%9}, {%0,%1,%2,%3};\n"
        : "+f"(d[0]), "+f"(d[1]), "+f"(d[2]), "+f"(d[3])
        : "r"(a[0]), "r"(a[1]), "r"(a[2]), "r"(a[3]), "r"(b[0]), "r"(b[1]));
}
__device__ __forceinline__ void cpa16(void* s, const void* g){
    u32 sa = (u32)__cvta_generic_to_shared(s);
    asm volatile("cp.async.cg.shared.global [%0], [%1], 16;\n" :: "r"(sa), "l"(g));
}

// -------- prep: x -> bf16 (normal + transposed plane); y==2 converts weights --------
__global__ __launch_bounds__(256) void k_prep(const float* __restrict__ x2,
                                              const float* __restrict__ x1,
                                              const float* __restrict__ qw,
                                              const float* __restrict__ kw,
                                              const float* __restrict__ vw){
    int t = threadIdx.x;
    if (blockIdx.y == 2){
        if (blockIdx.x >= 1280) return;
        int i = blockIdx.x * 256 + t;
        if (i < 128 * NC){
            int o = i >> 9, c = i & 511;
            g_wqk[i] = f2b(o < 64 ? qw[o*NC + c] : kw[(o-64)*NC + c]);
        } else {
            int j = i - 128*NC;
            g_wv[j] = f2b(vw[j]);
        }
        return;
    }
    int plane = blockIdx.x, which = blockIdx.y;
    const float* x = (which ? x1    : x2   ) + (size_t)plane * 4096;
    us16*       on = (which ? g_x1b : g_x2b) + (size_t)plane * 4096;
    us16*       ot = (which ? g_xT1 : g_xT2) + (size_t)plane * 4096;
    __shared__ float sm[64][65];
    const float4* x4 = (const float4*)x;
#pragma unroll
    for (int j = 0; j < 4; j++){
        int idx4 = j*256 + t;
        float4 v = x4[idx4];
        int h = idx4 >> 4, w4 = (idx4 & 15) * 4;
        sm[h][w4  ] = v.x; sm[h][w4+1] = v.y;
        sm[h][w4+2] = v.z; sm[h][w4+3] = v.w;
        ((uint2*)on)[idx4] = make_uint2(pk2(v.x, v.y), pk2(v.z, v.w));
    }
    __syncthreads();
#pragma unroll
    for (int j = 0; j < 4; j++){
        int idx4 = j*256 + t;
        int w = idx4 >> 4, h4 = (idx4 & 15) * 4;
        ((uint2*)ot)[idx4] = make_uint2(pk2(sm[h4][w],   sm[h4+1][w]),
                                        pk2(sm[h4+2][w], sm[h4+3][w]));
    }
}

// -------- gemm0: [q_w;k_w](128x512) * x2b -> q,k channel-last bf16 (+bias) --------
#define AS(st,i,j) smraw[(st)*7168 + (i)*56 + (j)]
#define BS(st,i,j) smraw[14336 + (st)*4352 + (i)*136 + (j)]
#define STG(p,c)   smraw[(p)*136 + (c)]
__global__ __launch_bounds__(256) void k_gemm0(
    const float* __restrict__ bias0, const float* __restrict__ bias1)
{
    __shared__ __align__(16) us16 smraw[23040];  // As[2][128][56] | Bs[2][32][136], reused as stg[128][136]
    int t = threadIdx.x;
    int n0 = blockIdx.y * 128;
    int b = blockIdx.z;
    const us16* A  = g_wqk;
    const us16* Bp = g_x2b + (size_t)b * CHW;

    int warp = t >> 5, lane = t & 31;
    int wm = warp >> 2, wn = warp & 3;
    int r = lane >> 2, cp = (lane & 3) * 2;

    int ar0 = t >> 2,        ac0 = (t & 3) * 8;
    int ar1 = (t+256) >> 2,  ac1 = ((t+256) & 3) * 8;
    int bk0 = t >> 4,        bn0 = (t & 15) * 8;
    int bk1 = (t+256) >> 4,  bn1 = ((t+256) & 15) * 8;

    float acc[4][4][4];
#pragma unroll
    for (int i = 0; i < 4; i++)
#pragma unroll
        for (int j = 0; j < 4; j++)
#pragma unroll
            for (int q2 = 0; q2 < 4; q2++) acc[i][j][q2] = 0.f;

    cpa16(&AS(0,ar0,ac0), A + (size_t)ar0*NC + ac0);
    cpa16(&AS(0,ar1,ac1), A + (size_t)ar1*NC + ac1);
    cpa16(&BS(0,bk0,bn0), Bp + (size_t)bk0*NHW + n0 + bn0);
    cpa16(&BS(0,bk1,bn1), Bp + (size_t)bk1*NHW + n0 + bn1);
    asm volatile("cp.async.commit_group;\n");

    for (int kt = 0; kt < 16; kt++){
        int cur = kt & 1;
        if (kt < 15){
            int k0 = (kt+1) * 32;
            int nx = cur ^ 1;
            cpa16(&AS(nx,ar0,ac0), A + (size_t)ar0*NC + k0 + ac0);
            cpa16(&AS(nx,ar1,ac1), A + (size_t)ar1*NC + k0 + ac1);
            cpa16(&BS(nx,bk0,bn0), Bp + (size_t)(k0+bk0)*NHW + n0 + bn0);
            cpa16(&BS(nx,bk1,bn1), Bp + (size_t)(k0+bk1)*NHW + n0 + bn1);
            asm volatile("cp.async.commit_group;\n");
            asm volatile("cp.async.wait_group 1;\n");
        } else {
            asm volatile("cp.async.wait_group 0;\n");
        }
        __syncthreads();
#pragma unroll
        for (int ks = 0; ks < 32; ks += 16){
            u32 af[4][4], bfr[4][2];
#pragma unroll
            for (int mi = 0; mi < 4; mi++){
                int rr = wm*64 + mi*16 + r;
                af[mi][0] = *(const u32*)&AS(cur, rr,   ks+cp  );
                af[mi][1] = *(const u32*)&AS(cur, rr+8, ks+cp  );
                af[mi][2] = *(const u32*)&AS(cur, rr,   ks+cp+8);
                af[mi][3] = *(const u32*)&AS(cur, rr+8, ks+cp+8);
            }
#pragma unroll
            for (int ni = 0; ni < 4; ni++){
                u32 sa = (u32)__cvta_generic_to_shared(&BS(cur, ks + (lane & 15), wn*32 + ni*8));
                asm volatile("ldmatrix.sync.aligned.m8n8.x2.trans.shared.b16 {%0,%1}, [%2];"
                             : "=r"(bfr[ni][0]), "=r"(bfr[ni][1]) : "r"(sa));
            }
#pragma unroll
            for (int mi = 0; mi < 4; mi++)
#pragma unroll
                for (int ni = 0; ni < 4; ni++)
                    mma_bf16(acc[mi][ni], af[mi], bfr[ni]);
        }
        __syncthreads();
    }

    // stage transpose (pixel-major) with bias, then coalesced channel-last write
#pragma unroll
    for (int mi = 0; mi < 4; mi++){
#pragma unroll
        for (int ni = 0; ni < 4; ni++){
            int pixl = wn*32 + ni*8 + cp;
#pragma unroll
            for (int rr2 = 0; rr2 < 2; rr2++){
                int ch = wm*64 + mi*16 + r + rr2*8;
                float bb = ch < 64 ? bias0[ch] : bias1[ch-64];
                STG(pixl,   ch) = f2b(acc[mi][ni][rr2*2 + 0] + bb);
                STG(pixl+1, ch) = f2b(acc[mi][ni][rr2*2 + 1] + bb);
            }
        }
    }
    __syncthreads();
    us16* dst = g_qkb + (size_t)b*NHW*128;
#pragma unroll
    for (int j = 0; j < 8; j++){
        int job = j*256 + t;
        int p = job >> 4, cseg = (job & 15) * 8;
        *(uint4*)(dst + (size_t)(n0+p)*128 + cseg) = *(uint4*)&STG(p, cseg);
    }
}

// -------- energies via mma: E[m][n] = sum_cq Q[pix_m][cq] * K[pix_n][cq] --------
__global__ __launch_bounds__(128) void k_energy(){
    __shared__ __align__(16) us16 QK[64][136];   // [pix_in_axis][128 ch + pad]
    int plane = blockIdx.x, b = blockIdx.y, dir = blockIdx.z, t = threadIdx.x;
    const us16* src = g_qkb + (size_t)b*NHW*128;
#pragma unroll
    for (int j = 0; j < 8; j++){
        int job = j*128 + t;
        int row = job >> 4, cseg = (job & 15) * 8;
        size_t pix = dir ? ((size_t)plane*64 + row) : ((size_t)row*64 + plane);
        *(uint4*)&QK[row][cseg] = *(const uint4*)(src + pix*128 + cseg);
    }
    __syncthreads();

    int warp = t >> 5, lane = t & 31;
    int r = lane >> 2, cp = (lane & 3) * 2;
    float acc[8][4];
#pragma unroll
    for (int nt = 0; nt < 8; nt++)
#pragma unroll
        for (int q2 = 0; q2 < 4; q2++) acc[nt][q2] = 0.f;

#pragma unroll
    for (int ks = 0; ks < 64; ks += 16){
        u32 af[4];
        int rr = warp*16 + r;
        af[0] = *(const u32*)&QK[rr  ][ks+cp  ];
        af[1] = *(const u32*)&QK[rr+8][ks+cp  ];
        af[2] = *(const u32*)&QK[rr  ][ks+cp+8];
        af[3] = *(const u32*)&QK[rr+8][ks+cp+8];
#pragma unroll
        for (int nt = 0; nt < 8; nt++){
            u32 bf2[2];
            int nn = nt*8 + r;
            bf2[0] = *(const u32*)&QK[nn][64+ks+cp  ];
            bf2[1] = *(const u32*)&QK[nn][64+ks+cp+8];
            mma_bf16(acc[nt], af, bf2);
        }
    }

    int joff = dir ? 64 : 0;
#pragma unroll
    for (int nt = 0; nt < 8; nt++){
        int n = nt*8 + cp;
#pragma unroll
        for (int rr2 = 0; rr2 < 2; rr2++){
            int m = warp*16 + r + rr2*8;
            size_t pix = dir ? ((size_t)b*4096 + (size_t)plane*64 + m)
                             : ((size_t)b*4096 + (size_t)m*64 + plane);
            *(float2*)&g_att[pix*128 + joff + n] =
                make_float2(acc[nt][rr2*2 + 0], acc[nt][rr2*2 + 1]);
        }
    }
}

// -------- softmax over 128, write bf16 --------
__global__ __launch_bounds__(256) void k_softmax(){
    int t = threadIdx.x;
    size_t pix = (size_t)blockIdx.x*8 + (t>>5);
    int lane = t & 31;
    float4 v = *(const float4*)(g_att + pix*128 + lane*4);
    float m = fmaxf(fmaxf(v.x, v.y), fmaxf(v.z, v.w));
#pragma unroll
    for (int o = 16; o; o >>= 1) m = fmaxf(m, __shfl_xor_sync(0xffffffffu, m, o));
    float e0 = __expf(v.x - m), e1 = __expf(v.y - m);
    float e2 = __expf(v.z - m), e3 = __expf(v.w - m);
    float s = e0 + e1 + e2 + e3;
#pragma unroll
    for (int o = 16; o; o >>= 1) s += __shfl_xor_sync(0xffffffffu, s, o);
    float inv = 1.f / s;
    u32 lo = pk2(e0*inv, e1*inv), hi = pk2(e2*inv, e3*inv);
    *(uint2*)(g_attb + pix*128 + lane*4) = make_uint2(lo, hi);
}

// -------- aggregation (channel-last out), cp.async pipelined, dir1 fuses merge --------
__global__ __launch_bounds__(256) void k_agg(int dir){
    __shared__ __align__(16) us16 Bs[64][72];
    __shared__ __align__(16) us16 As[2][128][72];
    int plane = blockIdx.x, b = blockIdx.y, t = threadIdx.x;
    const us16* X2 = (dir ? g_x2b : g_xT2) + (size_t)b*CHW + plane*64;
    const us16* X1 = (dir ? g_x1b : g_xT1) + (size_t)b*CHW + plane*64;
    const us16* attp; int istride;
    if (dir == 0){ attp = g_attb + ((size_t)b*4096 + plane)*128;                 istride = 8192; }
    else         { attp = g_attb + ((size_t)b*4096 + (size_t)plane*64)*128 + 64; istride = 128;  }

    int warp = t >> 5, lane = t & 31;
    int r = lane >> 2, cp = (lane & 3) * 2;

    {
        const us16* Xp = X2;
#pragma unroll
        for (int it = 0; it < 4; it++){
            int job = it*256 + t;
            int rr = job >> 3, seg = (job & 7) * 8;
            cpa16(&As[0][rr][seg], Xp + (size_t)rr*4096 + seg);
        }
        asm volatile("cp.async.commit_group;\n");
    }
#pragma unroll
    for (int it = 0; it < 2; it++){
        int job = it*256 + t;
        int i2 = job >> 3, seg = (job & 7) * 8;
        *(uint4*)&Bs[i2][seg] = *(const uint4*)(attp + (size_t)i2*istride + seg);
    }

    for (int i = 0; i < 8; i++){
        int cur = i & 1;
        if (i < 7){
            int c0n = ((i+1) >> 1) * 128, tseln = (i+1) & 1;
            const us16* Xp = (tseln ? X1 : X2) + (size_t)c0n * 4096;
            int nx = cur ^ 1;
#pragma unroll
            for (int it = 0; it < 4; it++){
                int job = it*256 + t;
                int rr = job >> 3, seg = (job & 7) * 8;
                cpa16(&As[nx][rr][seg], Xp + (size_t)rr*4096 + seg);
            }
            asm volatile("cp.async.commit_group;\n");
            asm volatile("cp.async.wait_group 1;\n");
        } else {
            asm volatile("cp.async.wait_group 0;\n");
        }
        __syncthreads();

        float acc[8][4];
#pragma unroll
        for (int nt = 0; nt < 8; nt++)
#pragma unroll
            for (int q2 = 0; q2 < 4; q2++) acc[nt][q2] = 0.f;
#pragma unroll
        for (int ks = 0; ks < 64; ks += 16){
            u32 af[4];
            int rr = warp*16 + r;
            af[0] = *(const u32*)&As[cur][rr  ][ks+cp  ];
            af[1] = *(const u32*)&As[cur][rr+8][ks+cp  ];
            af[2] = *(const u32*)&As[cur][rr  ][ks+cp+8];
            af[3] = *(const u32*)&As[cur][rr+8][ks+cp+8];
#pragma unroll
            for (int nt = 0; nt < 8; nt++){
                u32 bf2[2];
                int nn = nt*8 + r;
                bf2[0] = *(const u32*)&Bs[nn][ks+cp  ];
                bf2[1] = *(const u32*)&Bs[nn][ks+cp+8];
                mma_bf16(acc[nt], af, bf2);
            }
        }
        __syncthreads();

        us16* stg = &As[cur][0][0];
        int crow = warp*16 + r;
#pragma unroll
        for (int nt = 0; nt < 8; nt++){
            int n = nt*8 + cp;
            stg[n*136 + crow]         = f2b(acc[nt][0]);
            stg[(n+1)*136 + crow]     = f2b(acc[nt][1]);
            stg[n*136 + crow + 8]     = f2b(acc[nt][2]);
            stg[(n+1)*136 + crow + 8] = f2b(acc[nt][3]);
        }
        __syncthreads();

        int c0 = (i >> 1) * 128, tsel = i & 1;
        us16* dP = g_aggP + (size_t)tsel*BCHW + (size_t)b*CHW;
        us16* dF = g_aggF + (size_t)tsel*BCHW + (size_t)b*CHW;
#pragma unroll
        for (int it = 0; it < 4; it++){
            int job = it*256 + t;
            int n = job >> 4, cseg = (job & 15) * 8;
            uint4 s = *(uint4*)&stg[n*136 + cseg];
            size_t pix = dir ? ((size_t)plane*64 + n) : ((size_t)n*64 + plane);
            size_t off = pix*512 + c0 + cseg;
            if (dir == 0){
                *(uint4*)(dP + off) = s;
            } else {
                uint4 p = *(const uint4*)(dP + off);
                uint4 o4;
                o4.x = addbf2(s.x, p.x); o4.y = addbf2(s.y, p.y);
                o4.z = addbf2(s.z, p.z); o4.w = addbf2(s.w, p.w);
                *(uint4*)(dF + off) = o4;
            }
        }
        __syncthreads();
    }
}

// -------- output conv GEMM: v_w(512x512) * aggF(channel-last) + epilogue --------
__global__ __launch_bounds__(256) void k_gemm1(
    const float* __restrict__ vb, const float* __restrict__ x2r,
    const float* __restrict__ x1r, const float* __restrict__ gam,
    float* __restrict__ out)
{
    __shared__ __align__(16) us16 As2[2][128][40];
    __shared__ __align__(16) us16 Bs2[2][128][40];
    int t = threadIdx.x;
    int m0 = blockIdx.x * 128, n0 = blockIdx.y * 128;
    int b = blockIdx.z >> 1, sel = blockIdx.z & 1;
    const us16* A  = g_wv;
    const us16* Bp = g_aggF + (size_t)sel*BCHW + (size_t)b*CHW;

    int warp = t >> 5, lane = t & 31;
    int wm = warp >> 2, wn = warp & 3;
    int r = lane >> 2, cp = (lane & 3) * 2;

    int lr = t >> 2, lc = (t & 3) * 8;

    float acc[4][4][4];
#pragma unroll
    for (int i = 0; i < 4; i++)
#pragma unroll
        for (int j = 0; j < 4; j++)
#pragma unroll
            for (int q2 = 0; q2 < 4; q2++) acc[i][j][q2] = 0.f;

    cpa16(&As2[0][lr   ][lc], A  + (size_t)(m0+lr   )*NC  + lc);
    cpa16(&As2[0][lr+64][lc], A  + (size_t)(m0+lr+64)*NC  + lc);
    cpa16(&Bs2[0][lr   ][lc], Bp + (size_t)(n0+lr   )*512 + lc);
    cpa16(&Bs2[0][lr+64][lc], Bp + (size_t)(n0+lr+64)*512 + lc);
    asm volatile("cp.async.commit_group;\n");

    for (int kt = 0; kt < 16; kt++){
        int cur = kt & 1;
        if (kt < 15){
            int k0 = (kt+1) * 32;
            int nx = cur ^ 1;
            cpa16(&As2[nx][lr   ][lc], A  + (size_t)(m0+lr   )*NC  + k0 + lc);
            cpa16(&As2[nx][lr+64][lc], A  + (size_t)(m0+lr+64)*NC  + k0 + lc);
            cpa16(&Bs2[nx][lr   ][lc], Bp + (size_t)(n0+lr   )*512 + k0 + lc);
            cpa16(&Bs2[nx][lr+64][lc], Bp + (size_t)(n0+lr+64)*512 + k0 + lc);
            asm volatile("cp.async.commit_group;\n");
            asm volatile("cp.async.wait_group 1;\n");
        } else {
            asm volatile("cp.async.wait_group 0;\n");
        }
        __syncthreads();
#pragma unroll
        for (int ks = 0; ks < 32; ks += 16){
            u32 af[4][4], bfr[4][2];
#pragma unroll
            for (int mi = 0; mi < 4; mi++){
                int rr = wm*64 + mi*16 + r;
                af[mi][0] = *(const u32*)&As2[cur][rr  ][ks+cp  ];
                af[mi][1] = *(const u32*)&As2[cur][rr+8][ks+cp  ];
                af[mi][2] = *(const u32*)&As2[cur][rr  ][ks+cp+8];
                af[mi][3] = *(const u32*)&As2[cur][rr+8][ks+cp+8];
            }
#pragma unroll
            for (int ni = 0; ni < 4; ni++){
                int nn = wn*32 + ni*8 + r;
                bfr[ni][0] = *(const u32*)&Bs2[cur][nn][ks+cp  ];
                bfr[ni][1] = *(const u32*)&Bs2[cur][nn][ks+cp+8];
            }
#pragma unroll
            for (int mi = 0; mi < 4; mi++)
#pragma unroll
                for (int ni = 0; ni < 4; ni++)
                    mma_bf16(acc[mi][ni], af[mi], bfr[ni]);
        }
        __syncthreads();
    }

    float gval = gam[0];
    const float* xres = sel ? x1r : x2r;
    float* outp = out + (size_t)sel * BCHW;
#pragma unroll
    for (int mi = 0; mi < 4; mi++){
#pragma unroll
        for (int ni = 0; ni < 4; ni++){
            int ng = n0 + wn*32 + ni*8 + cp;
#pragma unroll
            for (int rr2 = 0; rr2 < 2; rr2++){
                int oo = m0 + wm*64 + mi*16 + r + rr2*8;
                float a0 = acc[mi][ni][rr2*2 + 0];
                float a1 = acc[mi][ni][rr2*2 + 1];
                float bb = vb[oo];
                size_t oi = (size_t)(b*NC + oo)*NHW + ng;
                float2 xr = *(const float2*)(xres + oi);
                *(float2*)(outp + oi) = make_float2(gval*(a0+bb)+xr.x, gval*(a1+bb)+xr.y);
            }
        }
    }
}

// ------------------------- launch -------------------------
extern "C" void kernel_launch(void* const* d_in, const int* in_sizes, int n_in,
                              void* d_out, int out_size){
    const float* x2    = (const float*)d_in[0];
    const float* x1    = (const float*)d_in[1];
    const float* q_w   = (const float*)d_in[2];
    const float* q_b   = (const float*)d_in[3];
    const float* k_w   = (const float*)d_in[4];
    const float* k_b   = (const float*)d_in[5];
    const float* v_w   = (const float*)d_in[6];
    const float* v_b   = (const float*)d_in[7];
    const float* gamma = (const float*)d_in[8];
    float* out = (float*)d_out;

    k_prep<<<dim3(NB*NC, 3), 256>>>(x2, x1, q_w, k_w, v_w);
    k_gemm0<<<dim3(1, 32, NB), 256>>>(q_b, k_b);
    k_energy<<<dim3(64, NB, 2), 128>>>();
    k_softmax<<<NB*4096/8, 256>>>();
    k_agg<<<dim3(64, NB), 256>>>(0);
    k_agg<<<dim3(64, NB), 256>>>(1);
    k_gemm1<<<dim3(4, 32, 16), 256>>>(v_b, x2, x1, gamma, out);
}

// round 9
// speedup vs baseline: 1.6026x; 1.0750x over previous
#include <cuda_runtime.h>
#include <cuda_bf16.h>

typedef unsigned int u32;
typedef unsigned short us16;

#define NB 8
#define NC 512
#define NQ 64
#define NHW 4096
#define BCHW (NB*NC*NHW)
#define CHW  (NC*NHW)

// ------------------------- device scratch -------------------------
__device__ __align__(16) us16  g_x2b [BCHW];
__device__ __align__(16) us16  g_x1b [BCHW];
__device__ __align__(16) us16  g_xT2 [BCHW];
__device__ __align__(16) us16  g_xT1 [BCHW];
__device__ __align__(16) us16  g_qkb [NB*NHW*128];   // [b][pix][q0..63,k0..63] bf16
__device__ __align__(16) float g_att [NB*NHW*128];   // only [0:64] (E_H) used
__device__ __align__(16) us16  g_attb[NB*NHW*128];
__device__ __align__(16) us16  g_aggP[2*BCHW];       // dir0 partial, channel-last
__device__ __align__(16) us16  g_aggF[2*BCHW];       // final agg, channel-last
__device__ __align__(16) us16  g_wqk[128*NC];
__device__ __align__(16) us16  g_wv [NC*NC];

// ------------------------- helpers -------------------------
__device__ __forceinline__ us16 f2b(float f){
    __nv_bfloat16 h = __float2bfloat16(f);
    return *reinterpret_cast<us16*>(&h);
}
__device__ __forceinline__ float b2f(us16 u){
    __nv_bfloat16 h; *reinterpret_cast<us16*>(&h) = u;
    return __bfloat162float(h);
}
__device__ __forceinline__ u32 pk2(float a, float b){
    return (u32)f2b(a) | ((u32)f2b(b) << 16);
}
__device__ __forceinline__ u32 addbf2(u32 s, u32 p){
    float lo = b2f((us16)(s & 0xffff)) + b2f((us16)(p & 0xffff));
    float hi = b2f((us16)(s >> 16))    + b2f((us16)(p >> 16));
    return pk2(lo, hi);
}
__device__ __forceinline__ void mma_bf16(float* d, const u32* a, const u32* b){
    asm volatile(
        "mma.sync.aligned.m16n8k16.row.col.f32.bf16.bf16.f32 "
        "{%0,%1,%2,%3}, {%4,%5,%6,%7}, {%8,%9}, {%0,%1,%2,%3};\n"
        : "+f"(d[0]), "+f"(d[1]), "+f"(d[2]), "+f"(d[3])
        : "r"(a[0]), "r"(a[1]), "r"(a[2]), "r"(a[3]), "r"(b[0]), "r"(b[1]));
}
__device__ __forceinline__ void cpa16(void* s, const void* g){
    u32 sa = (u32)__cvta_generic_to_shared(s);
    asm volatile("cp.async.cg.shared.global [%0], [%1], 16;\n" :: "r"(sa), "l"(g));
}

// -------- prep: x -> bf16 (normal + transposed plane); y==2 converts weights --------
__global__ __launch_bounds__(256) void k_prep(const float* __restrict__ x2,
                                              const float* __restrict__ x1,
                                              const float* __restrict__ qw,
                                              const float* __restrict__ kw,
                                              const float* __restrict__ vw){
    int t = threadIdx.x;
    if (blockIdx.y == 2){
        if (blockIdx.x >= 1280) return;
        int i = blockIdx.x * 256 + t;
        if (i < 128 * NC){
            int o = i >> 9, c = i & 511;
            g_wqk[i] = f2b(o < 64 ? qw[o*NC + c] : kw[(o-64)*NC + c]);
        } else {
            int j = i - 128*NC;
            g_wv[j] = f2b(vw[j]);
        }
        return;
    }
    int plane = blockIdx.x, which = blockIdx.y;
    const float* x = (which ? x1    : x2   ) + (size_t)plane * 4096;
    us16*       on = (which ? g_x1b : g_x2b) + (size_t)plane * 4096;
    us16*       ot = (which ? g_xT1 : g_xT2) + (size_t)plane * 4096;
    __shared__ float sm[64][65];
    const float4* x4 = (const float4*)x;
#pragma unroll
    for (int j = 0; j < 4; j++){
        int idx4 = j*256 + t;
        float4 v = x4[idx4];
        int h = idx4 >> 4, w4 = (idx4 & 15) * 4;
        sm[h][w4  ] = v.x; sm[h][w4+1] = v.y;
        sm[h][w4+2] = v.z; sm[h][w4+3] = v.w;
        ((uint2*)on)[idx4] = make_uint2(pk2(v.x, v.y), pk2(v.z, v.w));
    }
    __syncthreads();
#pragma unroll
    for (int j = 0; j < 4; j++){
        int idx4 = j*256 + t;
        int w = idx4 >> 4, h4 = (idx4 & 15) * 4;
        ((uint2*)ot)[idx4] = make_uint2(pk2(sm[h4][w],   sm[h4+1][w]),
                                        pk2(sm[h4+2][w], sm[h4+3][w]));
    }
}

// -------- gemm0: [q_w;k_w](128x512) * x2b -> q,k channel-last bf16 (+bias) --------
// K-chunk 64, 2-stage cp.async, single sync per iteration. Dynamic smem.
#define AS0(st,i,j) dsm[(st)*9216 + (i)*72 + (j)]
#define BS0(st,i,j) dsm[18432 + (st)*8704 + (i)*136 + (j)]
#define STG0(p,c)   dsm[(p)*136 + (c)]
#define GEMM0_SMEM ((18432 + 2*8704) * 2)
__global__ __launch_bounds__(256) void k_gemm0(
    const float* __restrict__ bias0, const float* __restrict__ bias1)
{
    extern __shared__ __align__(16) us16 dsm[];
    int t = threadIdx.x;
    int n0 = blockIdx.y * 128;
    int b = blockIdx.z;
    const us16* A  = g_wqk;
    const us16* Bp = g_x2b + (size_t)b * CHW;

    int warp = t >> 5, lane = t & 31;
    int wm = warp >> 2, wn = warp & 3;
    int r = lane >> 2, cp = (lane & 3) * 2;

    float acc[4][4][4];
#pragma unroll
    for (int i = 0; i < 4; i++)
#pragma unroll
        for (int j = 0; j < 4; j++)
#pragma unroll
            for (int q2 = 0; q2 < 4; q2++) acc[i][j][q2] = 0.f;

    // prologue: tile 0
#pragma unroll
    for (int it = 0; it < 4; it++){
        int job = it*256 + t;
        int ar = job >> 3, asg = (job & 7) * 8;       // A: 128 rows x 64 k
        cpa16(&AS0(0,ar,asg), A + (size_t)ar*NC + asg);
        int bk = job >> 4, bn = (job & 15) * 8;       // B: 64 k x 128 n
        cpa16(&BS0(0,bk,bn), Bp + (size_t)bk*NHW + n0 + bn);
    }
    asm volatile("cp.async.commit_group;\n");

    for (int kt = 0; kt < 8; kt++){
        int cur = kt & 1;
        asm volatile("cp.async.wait_group 0;\n");
        __syncthreads();
        if (kt < 7){
            int k0 = (kt+1) * 64;
            int nx = cur ^ 1;
#pragma unroll
            for (int it = 0; it < 4; it++){
                int job = it*256 + t;
                int ar = job >> 3, asg = (job & 7) * 8;
                cpa16(&AS0(nx,ar,asg), A + (size_t)ar*NC + k0 + asg);
                int bk = job >> 4, bn = (job & 15) * 8;
                cpa16(&BS0(nx,bk,bn), Bp + (size_t)(k0+bk)*NHW + n0 + bn);
            }
            asm volatile("cp.async.commit_group;\n");
        }
#pragma unroll
        for (int ks = 0; ks < 64; ks += 16){
            u32 af[4][4], bfr[4][2];
#pragma unroll
            for (int mi = 0; mi < 4; mi++){
                int rr = wm*64 + mi*16 + r;
                af[mi][0] = *(const u32*)&AS0(cur, rr,   ks+cp  );
                af[mi][1] = *(const u32*)&AS0(cur, rr+8, ks+cp  );
                af[mi][2] = *(const u32*)&AS0(cur, rr,   ks+cp+8);
                af[mi][3] = *(const u32*)&AS0(cur, rr+8, ks+cp+8);
            }
#pragma unroll
            for (int ni = 0; ni < 4; ni++){
                u32 sa = (u32)__cvta_generic_to_shared(&BS0(cur, ks + (lane & 15), wn*32 + ni*8));
                asm volatile("ldmatrix.sync.aligned.m8n8.x2.trans.shared.b16 {%0,%1}, [%2];"
                             : "=r"(bfr[ni][0]), "=r"(bfr[ni][1]) : "r"(sa));
            }
#pragma unroll
            for (int mi = 0; mi < 4; mi++)
#pragma unroll
                for (int ni = 0; ni < 4; ni++)
                    mma_bf16(acc[mi][ni], af[mi], bfr[ni]);
        }
    }
    __syncthreads();   // all compute done before stg overwrites smem

    // stage transpose (pixel-major) with bias, then coalesced channel-last write
#pragma unroll
    for (int mi = 0; mi < 4; mi++){
#pragma unroll
        for (int ni = 0; ni < 4; ni++){
            int pixl = wn*32 + ni*8 + cp;
#pragma unroll
            for (int rr2 = 0; rr2 < 2; rr2++){
                int ch = wm*64 + mi*16 + r + rr2*8;
                float bb = ch < 64 ? bias0[ch] : bias1[ch-64];
                STG0(pixl,   ch) = f2b(acc[mi][ni][rr2*2 + 0] + bb);
                STG0(pixl+1, ch) = f2b(acc[mi][ni][rr2*2 + 1] + bb);
            }
        }
    }
    __syncthreads();
    us16* dst = g_qkb + (size_t)b*NHW*128;
#pragma unroll
    for (int j = 0; j < 8; j++){
        int job = j*256 + t;
        int p = job >> 4, cseg = (job & 15) * 8;
        *(uint4*)(dst + (size_t)(n0+p)*128 + cseg) = *(uint4*)&STG0(p, cseg);
    }
}

// -------- energy dir0 (H direction): E_H[m][n] = sum_cq Q[pix_m]*K[pix_n], fixed w --------
__global__ __launch_bounds__(128) void k_energy0(){
    __shared__ __align__(16) us16 QK[64][136];
    int plane = blockIdx.x, b = blockIdx.y, t = threadIdx.x;
    const us16* src = g_qkb + (size_t)b*NHW*128;
#pragma unroll
    for (int j = 0; j < 8; j++){
        int job = j*128 + t;
        int row = job >> 4, cseg = (job & 15) * 8;
        size_t pix = (size_t)row*64 + plane;
        *(uint4*)&QK[row][cseg] = *(const uint4*)(src + pix*128 + cseg);
    }
    __syncthreads();

    int warp = t >> 5, lane = t & 31;
    int r = lane >> 2, cp = (lane & 3) * 2;
    float acc[8][4];
#pragma unroll
    for (int nt = 0; nt < 8; nt++)
#pragma unroll
        for (int q2 = 0; q2 < 4; q2++) acc[nt][q2] = 0.f;

#pragma unroll
    for (int ks = 0; ks < 64; ks += 16){
        u32 af[4];
        int rr = warp*16 + r;
        af[0] = *(const u32*)&QK[rr  ][ks+cp  ];
        af[1] = *(const u32*)&QK[rr+8][ks+cp  ];
        af[2] = *(const u32*)&QK[rr  ][ks+cp+8];
        af[3] = *(const u32*)&QK[rr+8][ks+cp+8];
#pragma unroll
        for (int nt = 0; nt < 8; nt++){
            u32 bf2[2];
            int nn = nt*8 + r;
            bf2[0] = *(const u32*)&QK[nn][64+ks+cp  ];
            bf2[1] = *(const u32*)&QK[nn][64+ks+cp+8];
            mma_bf16(acc[nt], af, bf2);
        }
    }

#pragma unroll
    for (int nt = 0; nt < 8; nt++){
        int n = nt*8 + cp;
#pragma unroll
        for (int rr2 = 0; rr2 < 2; rr2++){
            int m = warp*16 + r + rr2*8;
            size_t pix = (size_t)b*4096 + (size_t)m*64 + plane;
            *(float2*)&g_att[pix*128 + n] =
                make_float2(acc[nt][rr2*2 + 0], acc[nt][rr2*2 + 1]);
        }
    }
}

// -------- fused energy dir1 (W direction) + joint softmax over 128 --------
__global__ __launch_bounds__(128) void k_ensoft(){
    __shared__ __align__(16) us16 QK[64][136];
    __shared__ float EH[64][68];
    int plane = blockIdx.x, b = blockIdx.y, t = threadIdx.x;   // plane = h
    const us16* src = g_qkb + (size_t)b*NHW*128;
#pragma unroll
    for (int j = 0; j < 8; j++){
        int job = j*128 + t;
        int row = job >> 4, cseg = (job & 15) * 8;
        size_t pix = (size_t)plane*64 + row;
        *(uint4*)&QK[row][cseg] = *(const uint4*)(src + pix*128 + cseg);
    }
    const float* eh = g_att + ((size_t)b*4096 + (size_t)plane*64)*128;
#pragma unroll
    for (int j = 0; j < 8; j++){
        int job = j*128 + t;
        int row = job >> 4, c4 = (job & 15) * 4;
        *(float4*)&EH[row][c4] = *(const float4*)(eh + (size_t)row*128 + c4);
    }
    __syncthreads();

    int warp = t >> 5, lane = t & 31;
    int r = lane >> 2, cp = (lane & 3) * 2, cg = lane & 3;
    float acc[8][4];
#pragma unroll
    for (int nt = 0; nt < 8; nt++)
#pragma unroll
        for (int q2 = 0; q2 < 4; q2++) acc[nt][q2] = 0.f;

#pragma unroll
    for (int ks = 0; ks < 64; ks += 16){
        u32 af[4];
        int rr = warp*16 + r;
        af[0] = *(const u32*)&QK[rr  ][ks+cp  ];
        af[1] = *(const u32*)&QK[rr+8][ks+cp  ];
        af[2] = *(const u32*)&QK[rr  ][ks+cp+8];
        af[3] = *(const u32*)&QK[rr+8][ks+cp+8];
#pragma unroll
        for (int nt = 0; nt < 8; nt++){
            u32 bf2[2];
            int nn = nt*8 + r;
            bf2[0] = *(const u32*)&QK[nn][64+ks+cp  ];
            bf2[1] = *(const u32*)&QK[nn][64+ks+cp+8];
            mma_bf16(acc[nt], af, bf2);
        }
    }

    // joint softmax: row m owns 64 E_W (in regs across 4 lanes) + 64 E_H (smem)
#pragma unroll
    for (int rr2 = 0; rr2 < 2; rr2++){
        int m = warp*16 + r + rr2*8;
        float ew[16], ehv[16];
#pragma unroll
        for (int nt = 0; nt < 8; nt++){
            ew[nt*2]   = acc[nt][rr2*2];
            ew[nt*2+1] = acc[nt][rr2*2+1];
        }
        float mx = -1e30f;
#pragma unroll
        for (int u = 0; u < 16; u++){
            ehv[u] = EH[m][cg*16 + u];
            mx = fmaxf(mx, fmaxf(ew[u], ehv[u]));
        }
        mx = fmaxf(mx, __shfl_xor_sync(0xffffffffu, mx, 1));
        mx = fmaxf(mx, __shfl_xor_sync(0xffffffffu, mx, 2));
        float s = 0.f;
#pragma unroll
        for (int u = 0; u < 16; u++){
            ew[u]  = __expf(ew[u]  - mx);
            ehv[u] = __expf(ehv[u] - mx);
            s += ew[u] + ehv[u];
        }
        s += __shfl_xor_sync(0xffffffffu, s, 1);
        s += __shfl_xor_sync(0xffffffffu, s, 2);
        float inv = 1.f / s;
        us16* dst = g_attb + ((size_t)b*4096 + (size_t)plane*64 + m)*128;
#pragma unroll
        for (int u = 0; u < 16; u += 2)
            *(u32*)(dst + cg*16 + u) = pk2(ehv[u]*inv, ehv[u+1]*inv);
#pragma unroll
        for (int nt = 0; nt < 8; nt++)
            *(u32*)(dst + 64 + nt*8 + cp) = pk2(ew[nt*2]*inv, ew[nt*2+1]*inv);
    }
}

// -------- aggregation (channel-last out), cp.async pipelined, dir1 fuses merge --------
__global__ __launch_bounds__(256) void k_agg(int dir){
    __shared__ __align__(16) us16 Bs[64][72];
    __shared__ __align__(16) us16 As[2][128][72];
    int plane = blockIdx.x, b = blockIdx.y, t = threadIdx.x;
    const us16* X2 = (dir ? g_x2b : g_xT2) + (size_t)b*CHW + plane*64;
    const us16* X1 = (dir ? g_x1b : g_xT1) + (size_t)b*CHW + plane*64;
    const us16* attp; int istride;
    if (dir == 0){ attp = g_attb + ((size_t)b*4096 + plane)*128;                 istride = 8192; }
    else         { attp = g_attb + ((size_t)b*4096 + (size_t)plane*64)*128 + 64; istride = 128;  }

    int warp = t >> 5, lane = t & 31;
    int r = lane >> 2, cp = (lane & 3) * 2;

    {
        const us16* Xp = X2;
#pragma unroll
        for (int it = 0; it < 4; it++){
            int job = it*256 + t;
            int rr = job >> 3, seg = (job & 7) * 8;
            cpa16(&As[0][rr][seg], Xp + (size_t)rr*4096 + seg);
        }
        asm volatile("cp.async.commit_group;\n");
    }
#pragma unroll
    for (int it = 0; it < 2; it++){
        int job = it*256 + t;
        int i2 = job >> 3, seg = (job & 7) * 8;
        *(uint4*)&Bs[i2][seg] = *(const uint4*)(attp + (size_t)i2*istride + seg);
    }

    for (int i = 0; i < 8; i++){
        int cur = i & 1;
        if (i < 7){
            int c0n = ((i+1) >> 1) * 128, tseln = (i+1) & 1;
            const us16* Xp = (tseln ? X1 : X2) + (size_t)c0n * 4096;
            int nx = cur ^ 1;
#pragma unroll
            for (int it = 0; it < 4; it++){
                int job = it*256 + t;
                int rr = job >> 3, seg = (job & 7) * 8;
                cpa16(&As[nx][rr][seg], Xp + (size_t)rr*4096 + seg);
            }
            asm volatile("cp.async.commit_group;\n");
            asm volatile("cp.async.wait_group 1;\n");
        } else {
            asm volatile("cp.async.wait_group 0;\n");
        }
        __syncthreads();

        float acc[8][4];
#pragma unroll
        for (int nt = 0; nt < 8; nt++)
#pragma unroll
            for (int q2 = 0; q2 < 4; q2++) acc[nt][q2] = 0.f;
#pragma unroll
        for (int ks = 0; ks < 64; ks += 16){
            u32 af[4];
            int rr = warp*16 + r;
            af[0] = *(const u32*)&As[cur][rr  ][ks+cp  ];
            af[1] = *(const u32*)&As[cur][rr+8][ks+cp  ];
            af[2] = *(const u32*)&As[cur][rr  ][ks+cp+8];
            af[3] = *(const u32*)&As[cur][rr+8][ks+cp+8];
#pragma unroll
            for (int nt = 0; nt < 8; nt++){
                u32 bf2[2];
                int nn = nt*8 + r;
                bf2[0] = *(const u32*)&Bs[nn][ks+cp  ];
                bf2[1] = *(const u32*)&Bs[nn][ks+cp+8];
                mma_bf16(acc[nt], af, bf2);
            }
        }
        __syncthreads();

        us16* stg = &As[cur][0][0];
        int crow = warp*16 + r;
#pragma unroll
        for (int nt = 0; nt < 8; nt++){
            int n = nt*8 + cp;
            stg[n*136 + crow]         = f2b(acc[nt][0]);
            stg[(n+1)*136 + crow]     = f2b(acc[nt][1]);
            stg[n*136 + crow + 8]     = f2b(acc[nt][2]);
            stg[(n+1)*136 + crow + 8] = f2b(acc[nt][3]);
        }
        __syncthreads();

        int c0 = (i >> 1) * 128, tsel = i & 1;
        us16* dP = g_aggP + (size_t)tsel*BCHW + (size_t)b*CHW;
        us16* dF = g_aggF + (size_t)tsel*BCHW + (size_t)b*CHW;
#pragma unroll
        for (int it = 0; it < 4; it++){
            int job = it*256 + t;
            int n = job >> 4, cseg = (job & 15) * 8;
            uint4 s = *(uint4*)&stg[n*136 + cseg];
            size_t pix = dir ? ((size_t)plane*64 + n) : ((size_t)n*64 + plane);
            size_t off = pix*512 + c0 + cseg;
            if (dir == 0){
                *(uint4*)(dP + off) = s;
            } else {
                uint4 p = *(const uint4*)(dP + off);
                uint4 o4;
                o4.x = addbf2(s.x, p.x); o4.y = addbf2(s.y, p.y);
                o4.z = addbf2(s.z, p.z); o4.w = addbf2(s.w, p.w);
                *(uint4*)(dF + off) = o4;
            }
        }
        __syncthreads();
    }
}

// -------- output conv GEMM: v_w(512x512) * aggF(channel-last) + epilogue --------
// K-chunk 64, 2-stage cp.async, single sync per iteration. Dynamic smem.
#define AS1(st,i,j) dsm[(st)*9216 + (i)*72 + (j)]
#define BS1(st,i,j) dsm[18432 + (st)*9216 + (i)*72 + (j)]
#define GEMM1_SMEM (4*9216*2)
__global__ __launch_bounds__(256) void k_gemm1(
    const float* __restrict__ vb, const float* __restrict__ x2r,
    const float* __restrict__ x1r, const float* __restrict__ gam,
    float* __restrict__ out)
{
    extern __shared__ __align__(16) us16 dsm[];
    int t = threadIdx.x;
    int m0 = blockIdx.x * 128, n0 = blockIdx.y * 128;
    int b = blockIdx.z >> 1, sel = blockIdx.z & 1;
    const us16* A  = g_wv;
    const us16* Bp = g_aggF + (size_t)sel*BCHW + (size_t)b*CHW;

    int warp = t >> 5, lane = t & 31;
    int wm = warp >> 2, wn = warp & 3;
    int r = lane >> 2, cp = (lane & 3) * 2;

    float acc[4][4][4];
#pragma unroll
    for (int i = 0; i < 4; i++)
#pragma unroll
        for (int j = 0; j < 4; j++)
#pragma unroll
            for (int q2 = 0; q2 < 4; q2++) acc[i][j][q2] = 0.f;

#pragma unroll
    for (int it = 0; it < 4; it++){
        int job = it*256 + t;
        int rr = job >> 3, seg = (job & 7) * 8;
        cpa16(&AS1(0,rr,seg), A  + (size_t)(m0+rr)*NC  + seg);
        cpa16(&BS1(0,rr,seg), Bp + (size_t)(n0+rr)*512 + seg);
    }
    asm volatile("cp.async.commit_group;\n");

    for (int kt = 0; kt < 8; kt++){
        int cur = kt & 1;
        asm volatile("cp.async.wait_group 0;\n");
        __syncthreads();
        if (kt < 7){
            int k0 = (kt+1) * 64;
            int nx = cur ^ 1;
#pragma unroll
            for (int it = 0; it < 4; it++){
                int job = it*256 + t;
                int rr = job >> 3, seg = (job & 7) * 8;
                cpa16(&AS1(nx,rr,seg), A  + (size_t)(m0+rr)*NC  + k0 + seg);
                cpa16(&BS1(nx,rr,seg), Bp + (size_t)(n0+rr)*512 + k0 + seg);
            }
            asm volatile("cp.async.commit_group;\n");
        }
#pragma unroll
        for (int ks = 0; ks < 64; ks += 16){
            u32 af[4][4], bfr[4][2];
#pragma unroll
            for (int mi = 0; mi < 4; mi++){
                int rr = wm*64 + mi*16 + r;
                af[mi][0] = *(const u32*)&AS1(cur, rr,   ks+cp  );
                af[mi][1] = *(const u32*)&AS1(cur, rr+8, ks+cp  );
                af[mi][2] = *(const u32*)&AS1(cur, rr,   ks+cp+8);
                af[mi][3] = *(const u32*)&AS1(cur, rr+8, ks+cp+8);
            }
#pragma unroll
            for (int ni = 0; ni < 4; ni++){
                int nn = wn*32 + ni*8 + r;
                bfr[ni][0] = *(const u32*)&BS1(cur, nn, ks+cp  );
                bfr[ni][1] = *(const u32*)&BS1(cur, nn, ks+cp+8);
            }
#pragma unroll
            for (int mi = 0; mi < 4; mi++)
#pragma unroll
                for (int ni = 0; ni < 4; ni++)
                    mma_bf16(acc[mi][ni], af[mi], bfr[ni]);
        }
    }

    float gval = gam[0];
    const float* xres = sel ? x1r : x2r;
    float* outp = out + (size_t)sel * BCHW;
#pragma unroll
    for (int mi = 0; mi < 4; mi++){
#pragma unroll
        for (int ni = 0; ni < 4; ni++){
            int ng = n0 + wn*32 + ni*8 + cp;
#pragma unroll
            for (int rr2 = 0; rr2 < 2; rr2++){
                int oo = m0 + wm*64 + mi*16 + r + rr2*8;
                float a0 = acc[mi][ni][rr2*2 + 0];
                float a1 = acc[mi][ni][rr2*2 + 1];
                float bb = vb[oo];
                size_t oi = (size_t)(b*NC + oo)*NHW + ng;
                float2 xr = *(const float2*)(xres + oi);
                *(float2*)(outp + oi) = make_float2(gval*(a0+bb)+xr.x, gval*(a1+bb)+xr.y);
            }
        }
    }
}

// ------------------------- launch -------------------------
extern "C" void kernel_launch(void* const* d_in, const int* in_sizes, int n_in,
                              void* d_out, int out_size){
    const float* x2    = (const float*)d_in[0];
    const float* x1    = (const float*)d_in[1];
    const float* q_w   = (const float*)d_in[2];
    const float* q_b   = (const float*)d_in[3];
    const float* k_w   = (const float*)d_in[4];
    const float* k_b   = (const float*)d_in[5];
    const float* v_w   = (const float*)d_in[6];
    const float* v_b   = (const float*)d_in[7];
    const float* gamma = (const float*)d_in[8];
    float* out = (float*)d_out;

    cudaFuncSetAttribute(k_gemm0, cudaFuncAttributeMaxDynamicSharedMemorySize, GEMM0_SMEM);
    cudaFuncSetAttribute(k_gemm1, cudaFuncAttributeMaxDynamicSharedMemorySize, GEMM1_SMEM);

    k_prep<<<dim3(NB*NC, 3), 256>>>(x2, x1, q_w, k_w, v_w);
    k_gemm0<<<dim3(1, 32, NB), 256, GEMM0_SMEM>>>(q_b, k_b);
    k_energy0<<<dim3(64, NB), 128>>>();
    k_ensoft<<<dim3(64, NB), 128>>>();
    k_agg<<<dim3(64, NB), 256>>>(0);
    k_agg<<<dim3(64, NB), 256>>>(1);
    k_gemm1<<<dim3(4, 32, 16), 256, GEMM1_SMEM>>>(v_b, x2, x1, gamma, out);
}